// round 12
// baseline (speedup 1.0000x reference)
#include <cuda_runtime.h>
#include <cuda_bf16.h>
#include <math.h>
#include <stdint.h>

#define TSTEPS 80
#define BATCH  64
#define FDIM   4096
#define EDIM   512
#define HDIM   512
#define VDIM   13000
#define VPAD   13056
#define GDIM   2048
#define NSTEPS 160
#define MROWS  5120
#define START_ID 1

// ---------------- scratch ----------------
__device__ __align__(16) __nv_bfloat16 g_feats2[(size_t)MROWS * 2 * FDIM];   // [hi|lo]
__device__ __align__(16) __nv_bfloat16 g_Wf2   [(size_t)EDIM  * 2 * FDIM];
__device__ __align__(16) __nv_bfloat16 g_emb2  [(size_t)MROWS * 2 * EDIM];   // t-major rows
__device__ __align__(16) __nv_bfloat16 g_Wih2e [(size_t)GDIM  * 2 * EDIM];
__device__ __align__(16) __nv_bfloat16 g_Wih2d [(size_t)GDIM  * 2 * EDIM];
__device__ __align__(16) __nv_bfloat16 g_dece2 [(size_t)MROWS * 2 * EDIM];   // t-major rows
__device__ __align__(16) __nv_bfloat16 g_Whh2  [(size_t)GDIM  * 2 * HDIM];   // [hi|lo]
__device__ __align__(16) float         g_xgate [(size_t)NSTEPS * BATCH * GDIM]; // [s*64+b][2048]
__device__ __align__(16) __nv_bfloat16 g_hh2   [(size_t)MROWS * 2 * HDIM];   // t-major rows
__device__ __align__(16) __nv_bfloat16 g_Wo2   [(size_t)VPAD  * 2 * HDIM];
__device__ __align__(16) __nv_bfloat16 g_hbufb [2][BATCH * 1024];            // h ping-pong bf16 [hi|lo]
__device__ unsigned g_bar_cnt, g_bar_gen;      // lstm barrier (monotonic gen)
__device__ unsigned g_prog;                    // lstm progress, monotonic across replays
__device__ unsigned g_progbase;                // snapshot of g_prog at launch start

// ---------------- generic-PTX helpers ----------------
__device__ __forceinline__ uint32_t s2u(const void* p) {
    uint32_t a;
    asm("{ .reg .u64 t; cvta.to.shared.u64 t, %1; cvt.u32.u64 %0, t; }" : "=r"(a) : "l"(p));
    return a;
}
__device__ __forceinline__ void cpasync16(uint32_t dst, const void* src) {
    asm volatile("cp.async.cg.shared.global [%0], [%1], 16;" :: "r"(dst), "l"(src));
}
__device__ __forceinline__ void ldm4(uint32_t* d, uint32_t addr) {
    asm volatile("ldmatrix.sync.aligned.m8n8.x4.shared.b16 {%0,%1,%2,%3}, [%4];"
        : "=r"(d[0]), "=r"(d[1]), "=r"(d[2]), "=r"(d[3]) : "r"(addr));
}
__device__ __forceinline__ void mma16816(float* c, const uint32_t* a, const uint32_t* b) {
    asm volatile("mma.sync.aligned.m16n8k16.row.col.f32.bf16.bf16.f32 "
        "{%0,%1,%2,%3}, {%4,%5,%6,%7}, {%8,%9}, {%0,%1,%2,%3};"
        : "+f"(c[0]), "+f"(c[1]), "+f"(c[2]), "+f"(c[3])
        : "r"(a[0]), "r"(a[1]), "r"(a[2]), "r"(a[3]), "r"(b[0]), "r"(b[1]));
}
__device__ __forceinline__ void split_w4(__nv_bfloat16* dst, int K, float4 v) {
    float vv[4] = {v.x, v.y, v.z, v.w};
    __nv_bfloat16 hi[4], lo[4];
#pragma unroll
    for (int j = 0; j < 4; j++) {
        hi[j] = __float2bfloat16(vv[j]);
        lo[j] = __float2bfloat16(vv[j] - __bfloat162float(hi[j]));
    }
    *(uint64_t*)(dst)     = *(const uint64_t*)hi;
    *(uint64_t*)(dst + K) = *(const uint64_t*)lo;
}

// ---------------- prep: all splits + decoder gather + progress snapshot ----------------
#define B0 524288LL
#define B1 (B0 + 262144LL)
#define B2 (B1 + 262144LL)
#define B3 (B2 + 1671168LL)
#define B4 (B3 + 655360LL)
#define B5 (B4 + 262144LL)
#define B6 (B5 + 5242880LL)

__global__ void prep_all(const int* __restrict__ labels, const float* __restrict__ embed,
                         const float* __restrict__ W_frame, const float* __restrict__ W_ih,
                         const float* __restrict__ W_out, const float* __restrict__ W_hh,
                         const float* __restrict__ feats,
                         __nv_bfloat16* __restrict__ Wf2,
                         __nv_bfloat16* __restrict__ Wih2e, __nv_bfloat16* __restrict__ Wih2d,
                         __nv_bfloat16* __restrict__ Wo2, __nv_bfloat16* __restrict__ dece2,
                         __nv_bfloat16* __restrict__ Whh2, __nv_bfloat16* __restrict__ feats2)
{
    if (blockIdx.x == 0 && threadIdx.x == 0) {
        unsigned p;
        asm volatile("ld.relaxed.gpu.global.u32 %0, [%1];" : "=r"(p) : "l"(&g_prog) : "memory");
        asm volatile("st.relaxed.gpu.global.u32 [%0], %1;" :: "l"(&g_progbase), "r"(p) : "memory");
    }
    const long long stride = (long long)gridDim.x * blockDim.x;
    for (long long i = (long long)blockIdx.x * blockDim.x + threadIdx.x; i < B6; i += stride) {
        if (i < B0) {
            int r = (int)(i >> 10), c4 = ((int)i & 1023) << 2;
            float4 v = *(const float4*)(W_frame + (size_t)r * FDIM + c4);
            split_w4(Wf2 + (size_t)r * (2 * FDIM) + c4, FDIM, v);
        } else if (i < B2) {
            long long j = i - B0;
            int dec = (j >= 262144LL);
            if (dec) j -= 262144LL;
            int r = (int)(j >> 7), c4 = ((int)j & 127) << 2;
            float4 v = *(const float4*)(W_ih + (size_t)r * 1024 + (dec ? 512 : 0) + c4);
            split_w4((dec ? Wih2d : Wih2e) + (size_t)r * 1024 + c4, 512, v);
        } else if (i < B3) {
            long long j = i - B2;
            int r = (int)(j >> 7), c4 = ((int)j & 127) << 2;
            float4 v = make_float4(0.f, 0.f, 0.f, 0.f);
            if (r < VDIM) v = *(const float4*)(W_out + (size_t)r * HDIM + c4);
            split_w4(Wo2 + (size_t)r * 1024 + c4, 512, v);
        } else if (i < B4) {
            long long j = i - B3;
            int r = (int)(j >> 7), c4 = ((int)j & 127) << 2;   // r = t*64+b
            int t = r >> 6, b = r & 63;
            int id = (t == 0) ? START_ID : labels[b * TSTEPS + (t - 1)];
            float4 v = *(const float4*)(embed + (size_t)id * EDIM + c4);
            split_w4(dece2 + (size_t)r * 1024 + c4, 512, v);
        } else if (i < B5) {
            long long j = i - B4;
            int r = (int)(j >> 7), c4 = ((int)j & 127) << 2;
            float4 v = *(const float4*)(W_hh + (size_t)r * HDIM + c4);
            split_w4(Whh2 + (size_t)r * 1024 + c4, 512, v);
        } else {
            long long j = i - B5;
            int r = (int)(j >> 10), c4 = ((int)j & 1023) << 2;
            float4 v = *(const float4*)(feats + (size_t)r * FDIM + c4);
            split_w4(feats2 + (size_t)r * (2 * FDIM) + c4, FDIM, v);
        }
    }
}

// ---------------- mma.sync bf16 GEMM (embed + xgates), CTA tile 128x256 ----------------
#define STAGE 49152

__device__ __forceinline__ void ld_chunk(uint32_t sbase,
    const __nv_bfloat16* __restrict__ Ab, const __nv_bfloat16* __restrict__ Bb,
    int lda, int ao, int bo, int tid)
{
    const __nv_bfloat16* ap = Ab + ao;
    const __nv_bfloat16* bp = Bb + bo;
#pragma unroll
    for (int u = 0; u < 4; u++) {
        int idx = u * 256 + tid, r = idx >> 3, q = idx & 7;
        cpasync16(sbase + r * 128 + ((q ^ (r & 7)) << 4), ap + (size_t)r * lda + q * 8);
    }
#pragma unroll
    for (int u = 0; u < 8; u++) {
        int idx = u * 256 + tid, r = idx >> 3, q = idx & 7;
        cpasync16(sbase + 16384 + r * 128 + ((q ^ (r & 7)) << 4), bp + (size_t)r * lda + q * 8);
    }
}

__global__ __launch_bounds__(256, 1) void mma_tc(
    const __nv_bfloat16* __restrict__ A, const __nv_bfloat16* __restrict__ Aalt,
    int MsplitBlk, int rowOffAlt,
    const __nv_bfloat16* __restrict__ B, const __nv_bfloat16* __restrict__ Balt,
    const float* __restrict__ bias1, const float* __restrict__ bias2,
    void* __restrict__ Cv, int K, int Nreal, int ldc, int outMode, int outBf)
{
    extern __shared__ char smc[];
    const uint32_t sbase = s2u(smc);
    const int tid = threadIdx.x, lane = tid & 31, wid = tid >> 5;
    const int wn = wid & 3, wm = wid >> 2;
    const int bx = blockIdx.x;
    const bool alt = (Aalt != nullptr) && (bx >= MsplitBlk);
    const int m0 = (alt ? bx - MsplitBlk : bx) * 128;
    const int n0 = blockIdx.y * 256;
    const int rowOff = alt ? rowOffAlt : 0;
    const int lda = 2 * K;
    const int KC = K >> 6, NC = 3 * KC;
    const __nv_bfloat16* Ab = (alt ? Aalt : A) + (size_t)m0 * lda;
    const __nv_bfloat16* Bb = (alt ? Balt : B) + (size_t)n0 * lda;

    float acc[4][8][4];
#pragma unroll
    for (int a = 0; a < 4; a++)
#pragma unroll
        for (int b = 0; b < 8; b++)
#pragma unroll
            for (int d = 0; d < 4; d++) acc[a][b][d] = 0.f;

    ld_chunk(sbase, Ab, Bb, lda, 0, 0, tid);
    asm volatile("cp.async.commit_group;" ::: "memory");

    int segN = 0, kcN = 0;
    for (int c = 0; c < NC; c++) {
        asm volatile("cp.async.wait_group 0;" ::: "memory");
        __syncthreads();

        if (c + 1 < NC) {
            if (++kcN == KC) { kcN = 0; segN++; }
            int ao = ((segN == 2) ? K : 0) + (kcN << 6);
            int bo = ((segN == 1) ? K : 0) + (kcN << 6);
            ld_chunk(sbase + ((c + 1) & 1) * STAGE, Ab, Bb, lda, ao, bo, tid);
            asm volatile("cp.async.commit_group;" ::: "memory");
        }

        const uint32_t sa = sbase + (c & 1) * STAGE;
        const uint32_t sb = sa + 16384;
#pragma unroll
        for (int ks = 0; ks < 4; ks++) {
            uint32_t af[4][4];
#pragma unroll
            for (int mt = 0; mt < 4; mt++) {
                int r = wm * 64 + mt * 16 + (lane & 15);
                int q = 2 * ks + (lane >> 4);
                ldm4(af[mt], sa + r * 128 + ((q ^ (r & 7)) << 4));
            }
            uint32_t bf[4][4];
#pragma unroll
            for (int bp2 = 0; bp2 < 4; bp2++) {
                int r = wn * 64 + (bp2 * 2 + (lane >> 4)) * 8 + (lane & 7);
                int q = 2 * ks + ((lane >> 3) & 1);
                ldm4(bf[bp2], sb + r * 128 + ((q ^ (r & 7)) << 4));
            }
#pragma unroll
            for (int mt = 0; mt < 4; mt++)
#pragma unroll
                for (int nt = 0; nt < 8; nt++)
                    mma16816(acc[mt][nt], af[mt], &bf[nt >> 1][(nt & 1) * 2]);
        }
    }

    const int mb = m0 + wm * 64, nb = n0 + wn * 64;
#pragma unroll
    for (int mt = 0; mt < 4; mt++)
#pragma unroll
        for (int half = 0; half < 2; half++) {
            int r = mb + mt * 16 + (lane >> 2) + half * 8;
            int rr;
            if (outMode == 2) rr = (r % 80) * 64 + (r / 80);
            else              rr = r + rowOff;
#pragma unroll
            for (int nt = 0; nt < 8; nt++) {
                int cb = nb + nt * 8 + (lane & 3) * 2;
                if (cb < Nreal) {
                    float2 bv = *(const float2*)(bias1 + cb);
                    if (bias2) {
                        float2 b2 = *(const float2*)(bias2 + cb);
                        bv.x += b2.x; bv.y += b2.y;
                    }
                    float vx = acc[mt][nt][half * 2 + 0] + bv.x;
                    float vy = acc[mt][nt][half * 2 + 1] + bv.y;
                    if (outBf) {
                        __nv_bfloat16* op = (__nv_bfloat16*)Cv + (size_t)rr * ldc;
                        __nv_bfloat16 h0 = __float2bfloat16(vx), h1 = __float2bfloat16(vy);
                        __nv_bfloat16 l0 = __float2bfloat16(vx - __bfloat162float(h0));
                        __nv_bfloat16 l1 = __float2bfloat16(vy - __bfloat162float(h1));
                        *(__nv_bfloat162*)(op + cb)         = __halves2bfloat162(h0, h1);
                        *(__nv_bfloat162*)(op + Nreal + cb) = __halves2bfloat162(l0, l1);
                    } else {
                        float* op = (float*)Cv + (size_t)rr * ldc;
                        *(float2*)(op + cb) = make_float2(vx, vy);
                    }
                }
            }
        }
}

// ---------------- persistent LSTM on tensor cores (R9 structure + progress release) ----------------
#define LCTAS 64
#define SM_B_OFF 131072
#define SM_G_OFF 196608
#define SM_H_OFF (196608 + 64 * 33 * 4)
#define LSMEM    (SM_H_OFF + 2048)

__device__ __forceinline__ float sigf(float x) {
    return __fdividef(1.f, 1.f + __expf(-x));
}
__device__ __forceinline__ float tanhfast(float x) {
    float e = __expf(-2.f * fabsf(x));
    float t = __fdividef(1.f - e, 1.f + e);
    return copysignf(t, x);
}

__device__ __forceinline__ void gsync64()
{
    __syncthreads();
    if (threadIdx.x == 0) {
        unsigned gen;
        asm volatile("ld.relaxed.gpu.global.u32 %0, [%1];" : "=r"(gen) : "l"(&g_bar_gen) : "memory");
        unsigned old;
        asm volatile("atom.acq_rel.gpu.global.add.u32 %0, [%1], 1;"
                     : "=r"(old) : "l"(&g_bar_cnt) : "memory");
        if (old == LCTAS - 1) {
            asm volatile("st.relaxed.gpu.global.u32 [%0], %1;" :: "l"(&g_bar_cnt), "r"(0u) : "memory");
            asm volatile("st.release.gpu.global.u32 [%0], %1;" :: "l"(&g_bar_gen), "r"(gen + 1u) : "memory");
        } else {
            unsigned g;
            do {
                asm volatile("ld.acquire.gpu.global.u32 %0, [%1];" : "=r"(g) : "l"(&g_bar_gen) : "memory");
            } while (g == gen);
        }
    }
    __syncthreads();
}

__global__ __launch_bounds__(256, 1) void lstm_tc(
    const __nv_bfloat16* __restrict__ Whh2, const float* __restrict__ xg,
    __nv_bfloat16* __restrict__ hh2, __nv_bfloat16* __restrict__ hb)
{
    extern __shared__ char sml[];
    const uint32_t sb = s2u(sml);
    float* gs = (float*)(sml + SM_G_OFF);
    __nv_bfloat16* hex = (__nv_bfloat16*)(sml + SM_H_OFF);
    const int tid = threadIdx.x, lane = tid & 31, wid = tid >> 5;
    const int wm = wid & 3, wn = wid >> 2;     // 4 m-tiles(16) x 2 n-tiles(16)
    const int ct = blockIdx.x;

    unsigned base;
    asm volatile("ld.relaxed.gpu.global.u32 %0, [%1];" : "=r"(base) : "l"(&g_progbase) : "memory");

    // W tile: smem row n = h*4+g <- global row g*512 + ct*8 + h
#pragma unroll
    for (int u = 0; u < 16; u++) {
        int idx = u * 256 + tid;
        int n = idx >> 7, rem = idx & 127, pl = rem >> 3, q = rem & 7;
        int h = n >> 2, g = n & 3;
        cpasync16(sb + SM_B_OFF + pl * 4096 + n * 128 + ((q ^ (n & 7)) << 4),
                  Whh2 + (size_t)(g * 512 + ct * 8 + h) * 1024 + pl * 64 + q * 8);
    }
    asm volatile("cp.async.commit_group;" ::: "memory");
    *(uint64_t*)((char*)hb + ct * 2048 + tid * 8) = 0ull;   // zero hbuf[0]
    asm volatile("cp.async.wait_group 0;" ::: "memory");

    float c0 = 0.f, c1 = 0.f;
    gsync64();

    int cur = 0;
    for (int s = 0; s < NSTEPS; s++) {
        const __nv_bfloat16* hbc = hb + cur * (BATCH * 1024);
#pragma unroll
        for (int u = 0; u < 32; u++) {
            int idx = u * 256 + tid;
            int pl = idx >> 9, r = (idx >> 3) & 63, q = idx & 7;
            cpasync16(sb + pl * 8192 + r * 128 + ((q ^ (r & 7)) << 4),
                      hbc + (size_t)r * 1024 + pl * 64 + q * 8);
        }
        asm volatile("cp.async.commit_group;" ::: "memory");

        float xr[2][4];
#pragma unroll
        for (int p = 0; p < 2; p++) {
            int idx = tid + p * 256;
            int b = idx & 63, hl = idx >> 6;
            const float* xp = xg + (size_t)(s * 64 + b) * GDIM + ct * 8 + hl;
#pragma unroll
            for (int g = 0; g < 4; g++) xr[p][g] = __ldg(xp + g * 512);
        }

        asm volatile("cp.async.wait_group 0;" ::: "memory");
        __syncthreads();

        float acc[2][4];
#pragma unroll
        for (int nt = 0; nt < 2; nt++)
#pragma unroll
            for (int d = 0; d < 4; d++) acc[nt][d] = 0.f;

        // full-unroll 3-seg mainloop (R9 — fastest measured)
#pragma unroll
        for (int seg = 0; seg < 3; seg++) {
            const int pa = (seg == 2) ? 8 : 0;
            const int pb = (seg == 1) ? 8 : 0;
#pragma unroll
            for (int kc = 0; kc < 8; kc++) {
                const uint32_t abase = sb + (pa + kc) * 8192;
                const uint32_t bbase = sb + SM_B_OFF + (pb + kc) * 4096;
#pragma unroll
                for (int ks = 0; ks < 4; ks++) {
                    uint32_t af[4], bf[4];
                    {
                        int r = wm * 16 + (lane & 15);
                        int q = 2 * ks + (lane >> 4);
                        ldm4(af, abase + r * 128 + ((q ^ (r & 7)) << 4));
                    }
                    {
                        int r = wn * 16 + (lane >> 4) * 8 + (lane & 7);
                        int q = 2 * ks + ((lane >> 3) & 1);
                        ldm4(bf, bbase + r * 128 + ((q ^ (r & 7)) << 4));
                    }
                    mma16816(acc[0], af, &bf[0]);
                    mma16816(acc[1], af, &bf[2]);
                }
            }
        }

#pragma unroll
        for (int nt = 0; nt < 2; nt++) {
            int col = wn * 16 + nt * 8 + (lane & 3) * 2;
            int row = wm * 16 + (lane >> 2);
            gs[row * 33 + col]           = acc[nt][0];
            gs[row * 33 + col + 1]       = acc[nt][1];
            gs[(row + 8) * 33 + col]     = acc[nt][2];
            gs[(row + 8) * 33 + col + 1] = acc[nt][3];
        }
        __syncthreads();

#pragma unroll
        for (int p = 0; p < 2; p++) {
            int idx = tid + p * 256;
            int b = idx & 63, hl = idx >> 6;
            float gi = gs[b * 33 + hl * 4 + 0] + xr[p][0];
            float gf = gs[b * 33 + hl * 4 + 1] + xr[p][1];
            float gg = gs[b * 33 + hl * 4 + 2] + xr[p][2];
            float go = gs[b * 33 + hl * 4 + 3] + xr[p][3];
            float iv = sigf(gi), fv = sigf(gf), gv = tanhfast(gg), ov = sigf(go);
            float cc = (p ? c1 : c0);
            cc = fv * cc + iv * gv;
            if (p) c1 = cc; else c0 = cc;
            float hv = ov * tanhfast(cc);
            __nv_bfloat16 hbv = __float2bfloat16(hv);
            __nv_bfloat16 lbv = __float2bfloat16(hv - __bfloat162float(hbv));
            hex[b * 8 + hl]       = hbv;
            hex[512 + b * 8 + hl] = lbv;
        }
        __syncthreads();

        // coalesced 16B global stores
        if (tid < 128) {
            int half = tid >> 6, b = tid & 63;
            uint4 v = *(const uint4*)(hex + half * 512 + b * 8);
            __nv_bfloat16* hbn = hb + (cur ^ 1) * (BATCH * 1024);
            *(uint4*)(hbn + (size_t)b * 1024 + half * 512 + ct * 8) = v;
            if (s >= TSTEPS) {
                int t = s - TSTEPS;
                *(uint4*)(hh2 + (size_t)(t * 64 + b) * 1024 + half * 512 + ct * 8) = v;
            }
        }

        gsync64();
        if (ct == 0 && tid == 0) {
            unsigned pv = base + (unsigned)(s + 1);
            asm volatile("st.release.gpu.global.u32 [%0], %1;" :: "l"(&g_prog), "r"(pv) : "memory");
        }
        cur ^= 1;
    }
}

// ---------------- logits workers (separate kernel, gated on g_prog) ----------------
#define WCTAS 84
#define NJOBS (40 * 51)

__global__ __launch_bounds__(256, 1) void logits_worker(
    const __nv_bfloat16* __restrict__ hh2, const __nv_bfloat16* __restrict__ Wo2,
    const float* __restrict__ bout, float* __restrict__ out)
{
    extern __shared__ char smw[];
    const uint32_t sbase = s2u(smw);
    const int tid = threadIdx.x, lane = tid & 31, wid = tid >> 5;
    const int wn = wid & 3, wm = wid >> 2;
    const int cta = blockIdx.x;
    const int lda = 1024;   // 2*K, K=512

    unsigned base;
    asm volatile("ld.relaxed.gpu.global.u32 %0, [%1];" : "=r"(base) : "l"(&g_progbase) : "memory");

    for (int j = cta; j < NJOBS; j += WCTAS) {
        int mblk = j % 40, nblk = j / 40;
        int m0 = mblk * 128, n0 = nblk * 256;
        if (tid == 0) {
            unsigned tgt = base + (unsigned)(82 + 2 * mblk);
            unsigned g;
            do {
                asm volatile("ld.acquire.gpu.global.u32 %0, [%1];" : "=r"(g) : "l"(&g_prog) : "memory");
            } while ((int)(g - tgt) < 0);
        }
        __syncthreads();

        const __nv_bfloat16* Ab = hh2 + (size_t)m0 * lda;
        const __nv_bfloat16* Bb = Wo2 + (size_t)n0 * lda;

        float acc[4][8][4];
#pragma unroll
        for (int a = 0; a < 4; a++)
#pragma unroll
            for (int b = 0; b < 8; b++)
#pragma unroll
                for (int d = 0; d < 4; d++) acc[a][b][d] = 0.f;

        ld_chunk(sbase, Ab, Bb, lda, 0, 0, tid);
        asm volatile("cp.async.commit_group;" ::: "memory");

        int segN = 0, kcN = 0;
        for (int c = 0; c < 24; c++) {
            asm volatile("cp.async.wait_group 0;" ::: "memory");
            __syncthreads();
            if (c + 1 < 24) {
                if (++kcN == 8) { kcN = 0; segN++; }
                int ao = ((segN == 2) ? 512 : 0) + (kcN << 6);
                int bo = ((segN == 1) ? 512 : 0) + (kcN << 6);
                ld_chunk(sbase + ((c + 1) & 1) * STAGE, Ab, Bb, lda, ao, bo, tid);
                asm volatile("cp.async.commit_group;" ::: "memory");
            }
            const uint32_t sa = sbase + (c & 1) * STAGE;
            const uint32_t sB = sa + 16384;
#pragma unroll
            for (int ks = 0; ks < 4; ks++) {
                uint32_t af[4][4];
#pragma unroll
                for (int mt = 0; mt < 4; mt++) {
                    int r = wm * 64 + mt * 16 + (lane & 15);
                    int q = 2 * ks + (lane >> 4);
                    ldm4(af[mt], sa + r * 128 + ((q ^ (r & 7)) << 4));
                }
                uint32_t bf[4][4];
#pragma unroll
                for (int bp2 = 0; bp2 < 4; bp2++) {
                    int r = wn * 64 + (bp2 * 2 + (lane >> 4)) * 8 + (lane & 7);
                    int q = 2 * ks + ((lane >> 3) & 1);
                    ldm4(bf[bp2], sB + r * 128 + ((q ^ (r & 7)) << 4));
                }
#pragma unroll
                for (int mt = 0; mt < 4; mt++)
#pragma unroll
                    for (int nt = 0; nt < 8; nt++)
                        mma16816(acc[mt][nt], af[mt], &bf[nt >> 1][(nt & 1) * 2]);
            }
        }

        const int mb = m0 + wm * 64, nb = n0 + wn * 64;
#pragma unroll
        for (int mt = 0; mt < 4; mt++)
#pragma unroll
            for (int half = 0; half < 2; half++) {
                int r = mb + mt * 16 + (lane >> 2) + half * 8;
                int rr = (r & 63) * 80 + (r >> 6);   // t-major -> b*80+t
                float* op = out + (size_t)rr * VDIM;
#pragma unroll
                for (int nt = 0; nt < 8; nt++) {
                    int cb = nb + nt * 8 + (lane & 3) * 2;
                    if (cb < VDIM) {
                        float2 bv = *(const float2*)(bout + cb);
                        *(float2*)(op + cb) = make_float2(
                            acc[mt][nt][half * 2 + 0] + bv.x,
                            acc[mt][nt][half * 2 + 1] + bv.y);
                    }
                }
            }
        __syncthreads();
    }
}

// ---------------- launch ----------------
extern "C" void kernel_launch(void* const* d_in, const int* in_sizes, int n_in,
                              void* d_out, int out_size)
{
    const float* feats   = (const float*)d_in[0];
    const int*   labels  = (const int*)  d_in[1];
    const float* W_frame = (const float*)d_in[2];
    const float* b_frame = (const float*)d_in[3];
    const float* embed   = (const float*)d_in[4];
    const float* W_ih    = (const float*)d_in[5];
    const float* W_hh    = (const float*)d_in[6];
    const float* b_ih    = (const float*)d_in[7];
    const float* b_hh    = (const float*)d_in[8];
    const float* W_out   = (const float*)d_in[9];
    const float* b_out   = (const float*)d_in[10];
    float* out = (float*)d_out;

    float* p_xgate;
    __nv_bfloat16 *p_feats2, *p_Wf2, *p_emb2, *p_Wih2e, *p_Wih2d, *p_dece2, *p_Whh2, *p_hh2, *p_Wo2, *p_hb;
    cudaGetSymbolAddress((void**)&p_xgate,  g_xgate);
    cudaGetSymbolAddress((void**)&p_feats2, g_feats2);
    cudaGetSymbolAddress((void**)&p_Wf2,    g_Wf2);
    cudaGetSymbolAddress((void**)&p_emb2,   g_emb2);
    cudaGetSymbolAddress((void**)&p_Wih2e,  g_Wih2e);
    cudaGetSymbolAddress((void**)&p_Wih2d,  g_Wih2d);
    cudaGetSymbolAddress((void**)&p_dece2,  g_dece2);
    cudaGetSymbolAddress((void**)&p_Whh2,   g_Whh2);
    cudaGetSymbolAddress((void**)&p_hh2,    g_hh2);
    cudaGetSymbolAddress((void**)&p_Wo2,    g_Wo2);
    cudaGetSymbolAddress((void**)&p_hb,     g_hbufb);

    static cudaStream_t s2 = nullptr;
    static cudaEvent_t ev1 = nullptr, ev2 = nullptr;
    if (!s2) {
        cudaStreamCreateWithFlags(&s2, cudaStreamNonBlocking);
        cudaEventCreateWithFlags(&ev1, cudaEventDisableTiming);
        cudaEventCreateWithFlags(&ev2, cudaEventDisableTiming);
    }

    cudaFuncSetAttribute(lstm_tc, cudaFuncAttributeMaxDynamicSharedMemorySize, LSMEM);
    const int smem_tc = 2 * STAGE;
    cudaFuncSetAttribute(mma_tc, cudaFuncAttributeMaxDynamicSharedMemorySize, smem_tc);
    cudaFuncSetAttribute(logits_worker, cudaFuncAttributeMaxDynamicSharedMemorySize, smem_tc);

    // [0] all prep (snapshots g_progbase)
    prep_all<<<1480, 256>>>(labels, embed, W_frame, W_ih, W_out, W_hh, feats,
                            p_Wf2, p_Wih2e, p_Wih2d, p_Wo2, p_dece2, p_Whh2, p_feats2);
    // [1] frame embedding -> g_emb2 (bf16 dual, t-major rows), K=4096
    {
        dim3 grid(MROWS / 128, EDIM / 256);
        mma_tc<<<grid, 256, smem_tc>>>(p_feats2, nullptr, 1 << 30, 0, p_Wf2, nullptr,
                                       b_frame, nullptr, p_emb2, FDIM, EDIM, 2 * EDIM, 2, 1);
    }
    // [2] both x-gate GEMMs fused, K=512
    {
        dim3 grid(2 * (MROWS / 128), GDIM / 256);
        mma_tc<<<grid, 256, smem_tc>>>(p_emb2, p_dece2, MROWS / 128, MROWS,
                                       p_Wih2e, p_Wih2d, b_ih, b_hh,
                                       p_xgate, EDIM, GDIM, GDIM, 0, 0);
    }
    // fork: logits workers run concurrently with the recurrence
    cudaEventRecord(ev1, 0);
    cudaStreamWaitEvent(s2, ev1, 0);
    // [3] recurrence (default stream)  <-- profiled launch
    lstm_tc<<<LCTAS, 256, LSMEM>>>(p_Whh2, p_xgate, p_hh2, p_hb);
    // [4] gated logits workers (stream s2)
    logits_worker<<<WCTAS, 256, smem_tc, s2>>>(p_hh2, p_Wo2, b_out, out);
    // join
    cudaEventRecord(ev2, s2);
    cudaStreamWaitEvent(0, ev2, 0);
}

// round 13
// speedup vs baseline: 1.0018x; 1.0018x over previous
#include <cuda_runtime.h>
#include <cuda_bf16.h>
#include <math.h>
#include <stdint.h>

#define TSTEPS 80
#define BATCH  64
#define FDIM   4096
#define EDIM   512
#define HDIM   512
#define VDIM   13000
#define VPAD   13056
#define GDIM   2048
#define NSTEPS 160
#define MROWS  5120
#define START_ID 1

// ---------------- scratch ----------------
__device__ __align__(16) __nv_bfloat16 g_feats2[(size_t)MROWS * 2 * FDIM];   // [hi|lo]
__device__ __align__(16) __nv_bfloat16 g_Wf2   [(size_t)EDIM  * 2 * FDIM];
__device__ __align__(16) __nv_bfloat16 g_emb2  [(size_t)MROWS * 2 * EDIM];   // t-major rows
__device__ __align__(16) __nv_bfloat16 g_Wih2e [(size_t)GDIM  * 2 * EDIM];
__device__ __align__(16) __nv_bfloat16 g_Wih2d [(size_t)GDIM  * 2 * EDIM];
__device__ __align__(16) __nv_bfloat16 g_dece2 [(size_t)MROWS * 2 * EDIM];   // t-major rows
__device__ __align__(16) __nv_bfloat16 g_Whh2  [(size_t)GDIM  * 2 * HDIM];   // [hi|lo]
__device__ __align__(16) float         g_xgate [(size_t)NSTEPS * BATCH * GDIM]; // [s*64+b][2048]
__device__ __align__(16) __nv_bfloat16 g_hh2   [(size_t)MROWS * 2 * HDIM];   // t-major rows
__device__ __align__(16) __nv_bfloat16 g_Wo2   [(size_t)VPAD  * 2 * HDIM];
__device__ __align__(16) __nv_bfloat16 g_hbufb [2][BATCH * 1024];            // h ping-pong bf16 [hi|lo]
// each sync var on its own 256B-aligned line (kill false sharing between
// the LSTM barrier and the worker progress polling)
__device__ __align__(256) unsigned g_bar_cnt;
__device__ __align__(256) unsigned g_bar_gen;
__device__ __align__(256) unsigned g_prog;
__device__ __align__(256) unsigned g_progbase;

// ---------------- generic-PTX helpers ----------------
__device__ __forceinline__ uint32_t s2u(const void* p) {
    uint32_t a;
    asm("{ .reg .u64 t; cvta.to.shared.u64 t, %1; cvt.u32.u64 %0, t; }" : "=r"(a) : "l"(p));
    return a;
}
__device__ __forceinline__ void cpasync16(uint32_t dst, const void* src) {
    asm volatile("cp.async.cg.shared.global [%0], [%1], 16;" :: "r"(dst), "l"(src));
}
__device__ __forceinline__ void ldm4(uint32_t* d, uint32_t addr) {
    asm volatile("ldmatrix.sync.aligned.m8n8.x4.shared.b16 {%0,%1,%2,%3}, [%4];"
        : "=r"(d[0]), "=r"(d[1]), "=r"(d[2]), "=r"(d[3]) : "r"(addr));
}
__device__ __forceinline__ void mma16816(float* c, const uint32_t* a, const uint32_t* b) {
    asm volatile("mma.sync.aligned.m16n8k16.row.col.f32.bf16.bf16.f32 "
        "{%0,%1,%2,%3}, {%4,%5,%6,%7}, {%8,%9}, {%0,%1,%2,%3};"
        : "+f"(c[0]), "+f"(c[1]), "+f"(c[2]), "+f"(c[3])
        : "r"(a[0]), "r"(a[1]), "r"(a[2]), "r"(a[3]), "r"(b[0]), "r"(b[1]));
}
__device__ __forceinline__ void split_w4(__nv_bfloat16* dst, int K, float4 v) {
    float vv[4] = {v.x, v.y, v.z, v.w};
    __nv_bfloat16 hi[4], lo[4];
#pragma unroll
    for (int j = 0; j < 4; j++) {
        hi[j] = __float2bfloat16(vv[j]);
        lo[j] = __float2bfloat16(vv[j] - __bfloat162float(hi[j]));
    }
    *(uint64_t*)(dst)     = *(const uint64_t*)hi;
    *(uint64_t*)(dst + K) = *(const uint64_t*)lo;
}

// ---------------- prep: all splits + decoder gather + progress snapshot ----------------
#define B0 524288LL
#define B1 (B0 + 262144LL)
#define B2 (B1 + 262144LL)
#define B3 (B2 + 1671168LL)
#define B4 (B3 + 655360LL)
#define B5 (B4 + 262144LL)
#define B6 (B5 + 5242880LL)

__global__ void prep_all(const int* __restrict__ labels, const float* __restrict__ embed,
                         const float* __restrict__ W_frame, const float* __restrict__ W_ih,
                         const float* __restrict__ W_out, const float* __restrict__ W_hh,
                         const float* __restrict__ feats,
                         __nv_bfloat16* __restrict__ Wf2,
                         __nv_bfloat16* __restrict__ Wih2e, __nv_bfloat16* __restrict__ Wih2d,
                         __nv_bfloat16* __restrict__ Wo2, __nv_bfloat16* __restrict__ dece2,
                         __nv_bfloat16* __restrict__ Whh2, __nv_bfloat16* __restrict__ feats2)
{
    if (blockIdx.x == 0 && threadIdx.x == 0) {
        unsigned p;
        asm volatile("ld.relaxed.gpu.global.u32 %0, [%1];" : "=r"(p) : "l"(&g_prog) : "memory");
        asm volatile("st.relaxed.gpu.global.u32 [%0], %1;" :: "l"(&g_progbase), "r"(p) : "memory");
    }
    const long long stride = (long long)gridDim.x * blockDim.x;
    for (long long i = (long long)blockIdx.x * blockDim.x + threadIdx.x; i < B6; i += stride) {
        if (i < B0) {
            int r = (int)(i >> 10), c4 = ((int)i & 1023) << 2;
            float4 v = *(const float4*)(W_frame + (size_t)r * FDIM + c4);
            split_w4(Wf2 + (size_t)r * (2 * FDIM) + c4, FDIM, v);
        } else if (i < B2) {
            long long j = i - B0;
            int dec = (j >= 262144LL);
            if (dec) j -= 262144LL;
            int r = (int)(j >> 7), c4 = ((int)j & 127) << 2;
            float4 v = *(const float4*)(W_ih + (size_t)r * 1024 + (dec ? 512 : 0) + c4);
            split_w4((dec ? Wih2d : Wih2e) + (size_t)r * 1024 + c4, 512, v);
        } else if (i < B3) {
            long long j = i - B2;
            int r = (int)(j >> 7), c4 = ((int)j & 127) << 2;
            float4 v = make_float4(0.f, 0.f, 0.f, 0.f);
            if (r < VDIM) v = *(const float4*)(W_out + (size_t)r * HDIM + c4);
            split_w4(Wo2 + (size_t)r * 1024 + c4, 512, v);
        } else if (i < B4) {
            long long j = i - B3;
            int r = (int)(j >> 7), c4 = ((int)j & 127) << 2;   // r = t*64+b
            int t = r >> 6, b = r & 63;
            int id = (t == 0) ? START_ID : labels[b * TSTEPS + (t - 1)];
            float4 v = *(const float4*)(embed + (size_t)id * EDIM + c4);
            split_w4(dece2 + (size_t)r * 1024 + c4, 512, v);
        } else if (i < B5) {
            long long j = i - B4;
            int r = (int)(j >> 7), c4 = ((int)j & 127) << 2;
            float4 v = *(const float4*)(W_hh + (size_t)r * HDIM + c4);
            split_w4(Whh2 + (size_t)r * 1024 + c4, 512, v);
        } else {
            long long j = i - B5;
            int r = (int)(j >> 10), c4 = ((int)j & 1023) << 2;
            float4 v = *(const float4*)(feats + (size_t)r * FDIM + c4);
            split_w4(feats2 + (size_t)r * (2 * FDIM) + c4, FDIM, v);
        }
    }
}

// ---------------- mma.sync bf16 GEMM (embed + xgates), CTA tile 128x256 ----------------
#define STAGE 49152

__device__ __forceinline__ void ld_chunk(uint32_t sbase,
    const __nv_bfloat16* __restrict__ Ab, const __nv_bfloat16* __restrict__ Bb,
    int lda, int ao, int bo, int tid)
{
    const __nv_bfloat16* ap = Ab + ao;
    const __nv_bfloat16* bp = Bb + bo;
#pragma unroll
    for (int u = 0; u < 4; u++) {
        int idx = u * 256 + tid, r = idx >> 3, q = idx & 7;
        cpasync16(sbase + r * 128 + ((q ^ (r & 7)) << 4), ap + (size_t)r * lda + q * 8);
    }
#pragma unroll
    for (int u = 0; u < 8; u++) {
        int idx = u * 256 + tid, r = idx >> 3, q = idx & 7;
        cpasync16(sbase + 16384 + r * 128 + ((q ^ (r & 7)) << 4), bp + (size_t)r * lda + q * 8);
    }
}

__global__ __launch_bounds__(256, 1) void mma_tc(
    const __nv_bfloat16* __restrict__ A, const __nv_bfloat16* __restrict__ Aalt,
    int MsplitBlk, int rowOffAlt,
    const __nv_bfloat16* __restrict__ B, const __nv_bfloat16* __restrict__ Balt,
    const float* __restrict__ bias1, const float* __restrict__ bias2,
    void* __restrict__ Cv, int K, int Nreal, int ldc, int outMode, int outBf)
{
    extern __shared__ char smc[];
    const uint32_t sbase = s2u(smc);
    const int tid = threadIdx.x, lane = tid & 31, wid = tid >> 5;
    const int wn = wid & 3, wm = wid >> 2;
    const int bx = blockIdx.x;
    const bool alt = (Aalt != nullptr) && (bx >= MsplitBlk);
    const int m0 = (alt ? bx - MsplitBlk : bx) * 128;
    const int n0 = blockIdx.y * 256;
    const int rowOff = alt ? rowOffAlt : 0;
    const int lda = 2 * K;
    const int KC = K >> 6, NC = 3 * KC;
    const __nv_bfloat16* Ab = (alt ? Aalt : A) + (size_t)m0 * lda;
    const __nv_bfloat16* Bb = (alt ? Balt : B) + (size_t)n0 * lda;

    float acc[4][8][4];
#pragma unroll
    for (int a = 0; a < 4; a++)
#pragma unroll
        for (int b = 0; b < 8; b++)
#pragma unroll
            for (int d = 0; d < 4; d++) acc[a][b][d] = 0.f;

    ld_chunk(sbase, Ab, Bb, lda, 0, 0, tid);
    asm volatile("cp.async.commit_group;" ::: "memory");

    int segN = 0, kcN = 0;
    for (int c = 0; c < NC; c++) {
        asm volatile("cp.async.wait_group 0;" ::: "memory");
        __syncthreads();

        if (c + 1 < NC) {
            if (++kcN == KC) { kcN = 0; segN++; }
            int ao = ((segN == 2) ? K : 0) + (kcN << 6);
            int bo = ((segN == 1) ? K : 0) + (kcN << 6);
            ld_chunk(sbase + ((c + 1) & 1) * STAGE, Ab, Bb, lda, ao, bo, tid);
            asm volatile("cp.async.commit_group;" ::: "memory");
        }

        const uint32_t sa = sbase + (c & 1) * STAGE;
        const uint32_t sb = sa + 16384;
#pragma unroll
        for (int ks = 0; ks < 4; ks++) {
            uint32_t af[4][4];
#pragma unroll
            for (int mt = 0; mt < 4; mt++) {
                int r = wm * 64 + mt * 16 + (lane & 15);
                int q = 2 * ks + (lane >> 4);
                ldm4(af[mt], sa + r * 128 + ((q ^ (r & 7)) << 4));
            }
            uint32_t bf[4][4];
#pragma unroll
            for (int bp2 = 0; bp2 < 4; bp2++) {
                int r = wn * 64 + (bp2 * 2 + (lane >> 4)) * 8 + (lane & 7);
                int q = 2 * ks + ((lane >> 3) & 1);
                ldm4(bf[bp2], sb + r * 128 + ((q ^ (r & 7)) << 4));
            }
#pragma unroll
            for (int mt = 0; mt < 4; mt++)
#pragma unroll
                for (int nt = 0; nt < 8; nt++)
                    mma16816(acc[mt][nt], af[mt], &bf[nt >> 1][(nt & 1) * 2]);
        }
    }

    const int mb = m0 + wm * 64, nb = n0 + wn * 64;
#pragma unroll
    for (int mt = 0; mt < 4; mt++)
#pragma unroll
        for (int half = 0; half < 2; half++) {
            int r = mb + mt * 16 + (lane >> 2) + half * 8;
            int rr;
            if (outMode == 2) rr = (r % 80) * 64 + (r / 80);
            else              rr = r + rowOff;
#pragma unroll
            for (int nt = 0; nt < 8; nt++) {
                int cb = nb + nt * 8 + (lane & 3) * 2;
                if (cb < Nreal) {
                    float2 bv = *(const float2*)(bias1 + cb);
                    if (bias2) {
                        float2 b2 = *(const float2*)(bias2 + cb);
                        bv.x += b2.x; bv.y += b2.y;
                    }
                    float vx = acc[mt][nt][half * 2 + 0] + bv.x;
                    float vy = acc[mt][nt][half * 2 + 1] + bv.y;
                    if (outBf) {
                        __nv_bfloat16* op = (__nv_bfloat16*)Cv + (size_t)rr * ldc;
                        __nv_bfloat16 h0 = __float2bfloat16(vx), h1 = __float2bfloat16(vy);
                        __nv_bfloat16 l0 = __float2bfloat16(vx - __bfloat162float(h0));
                        __nv_bfloat16 l1 = __float2bfloat16(vy - __bfloat162float(h1));
                        *(__nv_bfloat162*)(op + cb)         = __halves2bfloat162(h0, h1);
                        *(__nv_bfloat162*)(op + Nreal + cb) = __halves2bfloat162(l0, l1);
                    } else {
                        float* op = (float*)Cv + (size_t)rr * ldc;
                        *(float2*)(op + cb) = make_float2(vx, vy);
                    }
                }
            }
        }
}

// ---------------- persistent LSTM on tensor cores ----------------
#define LCTAS 64
#define SM_B_OFF 131072
#define SM_G_OFF 196608
#define SM_H_OFF (196608 + 64 * 33 * 4)
#define LSMEM    (SM_H_OFF + 2048)

__device__ __forceinline__ float sigf(float x) {
    return __fdividef(1.f, 1.f + __expf(-x));
}
__device__ __forceinline__ float tanhfast(float x) {
    float e = __expf(-2.f * fabsf(x));
    float t = __fdividef(1.f - e, 1.f + e);
    return copysignf(t, x);
}

__device__ __forceinline__ void gsync64()
{
    __syncthreads();
    if (threadIdx.x == 0) {
        unsigned gen;
        asm volatile("ld.relaxed.gpu.global.u32 %0, [%1];" : "=r"(gen) : "l"(&g_bar_gen) : "memory");
        unsigned old;
        asm volatile("atom.acq_rel.gpu.global.add.u32 %0, [%1], 1;"
                     : "=r"(old) : "l"(&g_bar_cnt) : "memory");
        if (old == LCTAS - 1) {
            asm volatile("st.relaxed.gpu.global.u32 [%0], %1;" :: "l"(&g_bar_cnt), "r"(0u) : "memory");
            asm volatile("st.release.gpu.global.u32 [%0], %1;" :: "l"(&g_bar_gen), "r"(gen + 1u) : "memory");
        } else {
            unsigned g;
            do {
                asm volatile("ld.acquire.gpu.global.u32 %0, [%1];" : "=r"(g) : "l"(&g_bar_gen) : "memory");
            } while (g == gen);
        }
    }
    __syncthreads();
}

__global__ __launch_bounds__(256, 1) void lstm_tc(
    const __nv_bfloat16* __restrict__ Whh2, const float* __restrict__ xg,
    __nv_bfloat16* __restrict__ hh2, __nv_bfloat16* __restrict__ hb)
{
    extern __shared__ char sml[];
    const uint32_t sb = s2u(sml);
    float* gs = (float*)(sml + SM_G_OFF);
    __nv_bfloat16* hex = (__nv_bfloat16*)(sml + SM_H_OFF);
    const int tid = threadIdx.x, lane = tid & 31, wid = tid >> 5;
    const int wm = wid & 3, wn = wid >> 2;     // 4 m-tiles(16) x 2 n-tiles(16)
    const int ct = blockIdx.x;

    unsigned base;
    asm volatile("ld.relaxed.gpu.global.u32 %0, [%1];" : "=r"(base) : "l"(&g_progbase) : "memory");

    // W tile: smem row n = h*4+g <- global row g*512 + ct*8 + h
#pragma unroll
    for (int u = 0; u < 16; u++) {
        int idx = u * 256 + tid;
        int n = idx >> 7, rem = idx & 127, pl = rem >> 3, q = rem & 7;
        int h = n >> 2, g = n & 3;
        cpasync16(sb + SM_B_OFF + pl * 4096 + n * 128 + ((q ^ (n & 7)) << 4),
                  Whh2 + (size_t)(g * 512 + ct * 8 + h) * 1024 + pl * 64 + q * 8);
    }
    asm volatile("cp.async.commit_group;" ::: "memory");
    *(uint64_t*)((char*)hb + ct * 2048 + tid * 8) = 0ull;   // zero hbuf[0]
    asm volatile("cp.async.wait_group 0;" ::: "memory");

    float c0 = 0.f, c1 = 0.f;
    gsync64();

    int cur = 0;
    for (int s = 0; s < NSTEPS; s++) {
        const __nv_bfloat16* hbc = hb + cur * (BATCH * 1024);
#pragma unroll
        for (int u = 0; u < 32; u++) {
            int idx = u * 256 + tid;
            int pl = idx >> 9, r = (idx >> 3) & 63, q = idx & 7;
            cpasync16(sb + pl * 8192 + r * 128 + ((q ^ (r & 7)) << 4),
                      hbc + (size_t)r * 1024 + pl * 64 + q * 8);
        }
        asm volatile("cp.async.commit_group;" ::: "memory");

        float xr[2][4];
#pragma unroll
        for (int p = 0; p < 2; p++) {
            int idx = tid + p * 256;
            int b = idx & 63, hl = idx >> 6;
            const float* xp = xg + (size_t)(s * 64 + b) * GDIM + ct * 8 + hl;
#pragma unroll
            for (int g = 0; g < 4; g++) xr[p][g] = __ldg(xp + g * 512);
        }

        asm volatile("cp.async.wait_group 0;" ::: "memory");
        __syncthreads();

        float acc[2][4];
#pragma unroll
        for (int nt = 0; nt < 2; nt++)
#pragma unroll
            for (int d = 0; d < 4; d++) acc[nt][d] = 0.f;

#pragma unroll
        for (int seg = 0; seg < 3; seg++) {
            const int pa = (seg == 2) ? 8 : 0;
            const int pb = (seg == 1) ? 8 : 0;
#pragma unroll
            for (int kc = 0; kc < 8; kc++) {
                const uint32_t abase = sb + (pa + kc) * 8192;
                const uint32_t bbase = sb + SM_B_OFF + (pb + kc) * 4096;
#pragma unroll
                for (int ks = 0; ks < 4; ks++) {
                    uint32_t af[4], bf[4];
                    {
                        int r = wm * 16 + (lane & 15);
                        int q = 2 * ks + (lane >> 4);
                        ldm4(af, abase + r * 128 + ((q ^ (r & 7)) << 4));
                    }
                    {
                        int r = wn * 16 + (lane >> 4) * 8 + (lane & 7);
                        int q = 2 * ks + ((lane >> 3) & 1);
                        ldm4(bf, bbase + r * 128 + ((q ^ (r & 7)) << 4));
                    }
                    mma16816(acc[0], af, &bf[0]);
                    mma16816(acc[1], af, &bf[2]);
                }
            }
        }

#pragma unroll
        for (int nt = 0; nt < 2; nt++) {
            int col = wn * 16 + nt * 8 + (lane & 3) * 2;
            int row = wm * 16 + (lane >> 2);
            gs[row * 33 + col]           = acc[nt][0];
            gs[row * 33 + col + 1]       = acc[nt][1];
            gs[(row + 8) * 33 + col]     = acc[nt][2];
            gs[(row + 8) * 33 + col + 1] = acc[nt][3];
        }
        __syncthreads();

#pragma unroll
        for (int p = 0; p < 2; p++) {
            int idx = tid + p * 256;
            int b = idx & 63, hl = idx >> 6;
            float gi = gs[b * 33 + hl * 4 + 0] + xr[p][0];
            float gf = gs[b * 33 + hl * 4 + 1] + xr[p][1];
            float gg = gs[b * 33 + hl * 4 + 2] + xr[p][2];
            float go = gs[b * 33 + hl * 4 + 3] + xr[p][3];
            float iv = sigf(gi), fv = sigf(gf), gv = tanhfast(gg), ov = sigf(go);
            float cc = (p ? c1 : c0);
            cc = fv * cc + iv * gv;
            if (p) c1 = cc; else c0 = cc;
            float hv = ov * tanhfast(cc);
            __nv_bfloat16 hbv = __float2bfloat16(hv);
            __nv_bfloat16 lbv = __float2bfloat16(hv - __bfloat162float(hbv));
            hex[b * 8 + hl]       = hbv;
            hex[512 + b * 8 + hl] = lbv;
        }
        __syncthreads();

        if (tid < 128) {
            int half = tid >> 6, b = tid & 63;
            uint4 v = *(const uint4*)(hex + half * 512 + b * 8);
            __nv_bfloat16* hbn = hb + (cur ^ 1) * (BATCH * 1024);
            *(uint4*)(hbn + (size_t)b * 1024 + half * 512 + ct * 8) = v;
            if (s >= TSTEPS) {
                int t = s - TSTEPS;
                *(uint4*)(hh2 + (size_t)(t * 64 + b) * 1024 + half * 512 + ct * 8) = v;
            }
        }

        gsync64();
        if (ct == 0 && tid == 0) {
            unsigned pv = base + (unsigned)(s + 1);
            asm volatile("st.release.gpu.global.u32 [%0], %1;" :: "l"(&g_prog), "r"(pv) : "memory");
        }
        cur ^= 1;
    }
}

// ---------------- logits workers (gated on g_prog, throttled polling) ----------------
#define WCTAS 84
#define NJOBS (40 * 51)

__global__ __launch_bounds__(256, 1) void logits_worker(
    const __nv_bfloat16* __restrict__ hh2, const __nv_bfloat16* __restrict__ Wo2,
    const float* __restrict__ bout, float* __restrict__ out)
{
    extern __shared__ char smw[];
    const uint32_t sbase = s2u(smw);
    const int tid = threadIdx.x, lane = tid & 31, wid = tid >> 5;
    const int wn = wid & 3, wm = wid >> 2;
    const int cta = blockIdx.x;
    const int lda = 1024;   // 2*K, K=512

    unsigned base;
    asm volatile("ld.relaxed.gpu.global.u32 %0, [%1];" : "=r"(base) : "l"(&g_progbase) : "memory");

    for (int j = cta; j < NJOBS; j += WCTAS) {
        int mblk = j % 40, nblk = j / 40;
        int m0 = mblk * 128, n0 = nblk * 256;
        if (tid == 0) {
            unsigned tgt = base + (unsigned)(82 + 2 * mblk);
            for (;;) {
                unsigned g;
                asm volatile("ld.acquire.gpu.global.u32 %0, [%1];" : "=r"(g) : "l"(&g_prog) : "memory");
                if ((int)(g - tgt) >= 0) break;
                __nanosleep(256);       // throttle: keep the progress line quiet
            }
        }
        __syncthreads();

        const __nv_bfloat16* Ab = hh2 + (size_t)m0 * lda;
        const __nv_bfloat16* Bb = Wo2 + (size_t)n0 * lda;

        float acc[4][8][4];
#pragma unroll
        for (int a = 0; a < 4; a++)
#pragma unroll
            for (int b = 0; b < 8; b++)
#pragma unroll
                for (int d = 0; d < 4; d++) acc[a][b][d] = 0.f;

        ld_chunk(sbase, Ab, Bb, lda, 0, 0, tid);
        asm volatile("cp.async.commit_group;" ::: "memory");

        int segN = 0, kcN = 0;
        for (int c = 0; c < 24; c++) {
            asm volatile("cp.async.wait_group 0;" ::: "memory");
            __syncthreads();
            if (c + 1 < 24) {
                if (++kcN == 8) { kcN = 0; segN++; }
                int ao = ((segN == 2) ? 512 : 0) + (kcN << 6);
                int bo = ((segN == 1) ? 512 : 0) + (kcN << 6);
                ld_chunk(sbase + ((c + 1) & 1) * STAGE, Ab, Bb, lda, ao, bo, tid);
                asm volatile("cp.async.commit_group;" ::: "memory");
            }
            const uint32_t sa = sbase + (c & 1) * STAGE;
            const uint32_t sB = sa + 16384;
#pragma unroll
            for (int ks = 0; ks < 4; ks++) {
                uint32_t af[4][4];
#pragma unroll
                for (int mt = 0; mt < 4; mt++) {
                    int r = wm * 64 + mt * 16 + (lane & 15);
                    int q = 2 * ks + (lane >> 4);
                    ldm4(af[mt], sa + r * 128 + ((q ^ (r & 7)) << 4));
                }
                uint32_t bf[4][4];
#pragma unroll
                for (int bp2 = 0; bp2 < 4; bp2++) {
                    int r = wn * 64 + (bp2 * 2 + (lane >> 4)) * 8 + (lane & 7);
                    int q = 2 * ks + ((lane >> 3) & 1);
                    ldm4(bf[bp2], sB + r * 128 + ((q ^ (r & 7)) << 4));
                }
#pragma unroll
                for (int mt = 0; mt < 4; mt++)
#pragma unroll
                    for (int nt = 0; nt < 8; nt++)
                        mma16816(acc[mt][nt], af[mt], &bf[nt >> 1][(nt & 1) * 2]);
            }
        }

        const int mb = m0 + wm * 64, nb = n0 + wn * 64;
#pragma unroll
        for (int mt = 0; mt < 4; mt++)
#pragma unroll
            for (int half = 0; half < 2; half++) {
                int r = mb + mt * 16 + (lane >> 2) + half * 8;
                int rr = (r & 63) * 80 + (r >> 6);   // t-major -> b*80+t
                float* op = out + (size_t)rr * VDIM;
#pragma unroll
                for (int nt = 0; nt < 8; nt++) {
                    int cb = nb + nt * 8 + (lane & 3) * 2;
                    if (cb < VDIM) {
                        float2 bv = *(const float2*)(bout + cb);
                        *(float2*)(op + cb) = make_float2(
                            acc[mt][nt][half * 2 + 0] + bv.x,
                            acc[mt][nt][half * 2 + 1] + bv.y);
                    }
                }
            }
        __syncthreads();
    }
}

// ---------------- launch ----------------
extern "C" void kernel_launch(void* const* d_in, const int* in_sizes, int n_in,
                              void* d_out, int out_size)
{
    const float* feats   = (const float*)d_in[0];
    const int*   labels  = (const int*)  d_in[1];
    const float* W_frame = (const float*)d_in[2];
    const float* b_frame = (const float*)d_in[3];
    const float* embed   = (const float*)d_in[4];
    const float* W_ih    = (const float*)d_in[5];
    const float* W_hh    = (const float*)d_in[6];
    const float* b_ih    = (const float*)d_in[7];
    const float* b_hh    = (const float*)d_in[8];
    const float* W_out   = (const float*)d_in[9];
    const float* b_out   = (const float*)d_in[10];
    float* out = (float*)d_out;

    float* p_xgate;
    __nv_bfloat16 *p_feats2, *p_Wf2, *p_emb2, *p_Wih2e, *p_Wih2d, *p_dece2, *p_Whh2, *p_hh2, *p_Wo2, *p_hb;
    cudaGetSymbolAddress((void**)&p_xgate,  g_xgate);
    cudaGetSymbolAddress((void**)&p_feats2, g_feats2);
    cudaGetSymbolAddress((void**)&p_Wf2,    g_Wf2);
    cudaGetSymbolAddress((void**)&p_emb2,   g_emb2);
    cudaGetSymbolAddress((void**)&p_Wih2e,  g_Wih2e);
    cudaGetSymbolAddress((void**)&p_Wih2d,  g_Wih2d);
    cudaGetSymbolAddress((void**)&p_dece2,  g_dece2);
    cudaGetSymbolAddress((void**)&p_Whh2,   g_Whh2);
    cudaGetSymbolAddress((void**)&p_hh2,    g_hh2);
    cudaGetSymbolAddress((void**)&p_Wo2,    g_Wo2);
    cudaGetSymbolAddress((void**)&p_hb,     g_hbufb);

    static cudaStream_t s2 = nullptr;
    static cudaEvent_t ev1 = nullptr, ev2 = nullptr;
    if (!s2) {
        cudaStreamCreateWithFlags(&s2, cudaStreamNonBlocking);
        cudaEventCreateWithFlags(&ev1, cudaEventDisableTiming);
        cudaEventCreateWithFlags(&ev2, cudaEventDisableTiming);
    }

    cudaFuncSetAttribute(lstm_tc, cudaFuncAttributeMaxDynamicSharedMemorySize, LSMEM);
    const int smem_tc = 2 * STAGE;
    cudaFuncSetAttribute(mma_tc, cudaFuncAttributeMaxDynamicSharedMemorySize, smem_tc);
    cudaFuncSetAttribute(logits_worker, cudaFuncAttributeMaxDynamicSharedMemorySize, smem_tc);

    // [0] all prep (snapshots g_progbase)
    prep_all<<<1480, 256>>>(labels, embed, W_frame, W_ih, W_out, W_hh, feats,
                            p_Wf2, p_Wih2e, p_Wih2d, p_Wo2, p_dece2, p_Whh2, p_feats2);
    // [1] frame embedding -> g_emb2 (bf16 dual, t-major rows), K=4096
    {
        dim3 grid(MROWS / 128, EDIM / 256);
        mma_tc<<<grid, 256, smem_tc>>>(p_feats2, nullptr, 1 << 30, 0, p_Wf2, nullptr,
                                       b_frame, nullptr, p_emb2, FDIM, EDIM, 2 * EDIM, 2, 1);
    }
    // [2] both x-gate GEMMs fused, K=512
    {
        dim3 grid(2 * (MROWS / 128), GDIM / 256);
        mma_tc<<<grid, 256, smem_tc>>>(p_emb2, p_dece2, MROWS / 128, MROWS,
                                       p_Wih2e, p_Wih2d, b_ih, b_hh,
                                       p_xgate, EDIM, GDIM, GDIM, 0, 0);
    }
    // fork: logits workers run concurrently with the recurrence
    cudaEventRecord(ev1, 0);
    cudaStreamWaitEvent(s2, ev1, 0);
    // [3] recurrence (default stream)  <-- profiled launch
    lstm_tc<<<LCTAS, 256, LSMEM>>>(p_Whh2, p_xgate, p_hh2, p_hb);
    // [4] gated logits workers (stream s2)
    logits_worker<<<WCTAS, 256, smem_tc, s2>>>(p_hh2, p_Wo2, b_out, out);
    // join
    cudaEventRecord(ev2, s2);
    cudaStreamWaitEvent(0, ev2, 0);
}

// round 14
// speedup vs baseline: 1.0083x; 1.0065x over previous
#include <cuda_runtime.h>
#include <cuda_bf16.h>
#include <math.h>
#include <stdint.h>

#define TSTEPS 80
#define BATCH  64
#define FDIM   4096
#define EDIM   512
#define HDIM   512
#define VDIM   13000
#define VPAD   13056
#define GDIM   2048
#define NSTEPS 160
#define MROWS  5120
#define START_ID 1

// ---------------- scratch ----------------
__device__ __align__(16) __nv_bfloat16 g_feats2[(size_t)MROWS * 2 * FDIM];   // [hi|lo]
__device__ __align__(16) __nv_bfloat16 g_Wf2   [(size_t)EDIM  * 2 * FDIM];
__device__ __align__(16) __nv_bfloat16 g_emb2  [(size_t)MROWS * 2 * EDIM];   // t-major rows
__device__ __align__(16) __nv_bfloat16 g_Wih2e [(size_t)GDIM  * 2 * EDIM];
__device__ __align__(16) __nv_bfloat16 g_Wih2d [(size_t)GDIM  * 2 * EDIM];
__device__ __align__(16) __nv_bfloat16 g_dece2 [(size_t)MROWS * 2 * EDIM];   // t-major rows
__device__ __align__(16) __nv_bfloat16 g_Whh2  [(size_t)GDIM  * 2 * HDIM];   // [hi|lo]
__device__ __align__(16) float         g_xgate [(size_t)NSTEPS * BATCH * GDIM]; // [s*64+b][2048]
__device__ __align__(16) __nv_bfloat16 g_hh2   [(size_t)MROWS * 2 * HDIM];   // t-major rows
__device__ __align__(16) __nv_bfloat16 g_Wo2   [(size_t)VPAD  * 2 * HDIM];
__device__ __align__(16) __nv_bfloat16 g_hbufb [2][BATCH * 1024];            // h ping-pong bf16 [hi|lo]
// sync vars each on a private 256B line
__device__ __align__(256) unsigned g_bar_cnt;
__device__ __align__(256) unsigned g_bar_gen;
__device__ __align__(256) unsigned g_prog;
__device__ __align__(256) unsigned g_progbase;

// ---------------- generic-PTX helpers ----------------
__device__ __forceinline__ uint32_t s2u(const void* p) {
    uint32_t a;
    asm("{ .reg .u64 t; cvta.to.shared.u64 t, %1; cvt.u32.u64 %0, t; }" : "=r"(a) : "l"(p));
    return a;
}
__device__ __forceinline__ void cpasync16(uint32_t dst, const void* src) {
    asm volatile("cp.async.cg.shared.global [%0], [%1], 16;" :: "r"(dst), "l"(src));
}
__device__ __forceinline__ void ldm4(uint32_t* d, uint32_t addr) {
    asm volatile("ldmatrix.sync.aligned.m8n8.x4.shared.b16 {%0,%1,%2,%3}, [%4];"
        : "=r"(d[0]), "=r"(d[1]), "=r"(d[2]), "=r"(d[3]) : "r"(addr));
}
__device__ __forceinline__ void mma16816(float* c, const uint32_t* a, const uint32_t* b) {
    asm volatile("mma.sync.aligned.m16n8k16.row.col.f32.bf16.bf16.f32 "
        "{%0,%1,%2,%3}, {%4,%5,%6,%7}, {%8,%9}, {%0,%1,%2,%3};"
        : "+f"(c[0]), "+f"(c[1]), "+f"(c[2]), "+f"(c[3])
        : "r"(a[0]), "r"(a[1]), "r"(a[2]), "r"(a[3]), "r"(b[0]), "r"(b[1]));
}
__device__ __forceinline__ void split_w4(__nv_bfloat16* dst, int K, float4 v) {
    float vv[4] = {v.x, v.y, v.z, v.w};
    __nv_bfloat16 hi[4], lo[4];
#pragma unroll
    for (int j = 0; j < 4; j++) {
        hi[j] = __float2bfloat16(vv[j]);
        lo[j] = __float2bfloat16(vv[j] - __bfloat162float(hi[j]));
    }
    *(uint64_t*)(dst)     = *(const uint64_t*)hi;
    *(uint64_t*)(dst + K) = *(const uint64_t*)lo;
}

// ---------------- prep ----------------
#define B0 524288LL
#define B1 (B0 + 262144LL)
#define B2 (B1 + 262144LL)
#define B3 (B2 + 1671168LL)
#define B4 (B3 + 655360LL)
#define B5 (B4 + 262144LL)
#define B6 (B5 + 5242880LL)

__global__ void prep_all(const int* __restrict__ labels, const float* __restrict__ embed,
                         const float* __restrict__ W_frame, const float* __restrict__ W_ih,
                         const float* __restrict__ W_out, const float* __restrict__ W_hh,
                         const float* __restrict__ feats,
                         __nv_bfloat16* __restrict__ Wf2,
                         __nv_bfloat16* __restrict__ Wih2e, __nv_bfloat16* __restrict__ Wih2d,
                         __nv_bfloat16* __restrict__ Wo2, __nv_bfloat16* __restrict__ dece2,
                         __nv_bfloat16* __restrict__ Whh2, __nv_bfloat16* __restrict__ feats2)
{
    if (blockIdx.x == 0 && threadIdx.x == 0) {
        unsigned p;
        asm volatile("ld.relaxed.gpu.global.u32 %0, [%1];" : "=r"(p) : "l"(&g_prog) : "memory");
        asm volatile("st.relaxed.gpu.global.u32 [%0], %1;" :: "l"(&g_progbase), "r"(p) : "memory");
    }
    const long long stride = (long long)gridDim.x * blockDim.x;
    for (long long i = (long long)blockIdx.x * blockDim.x + threadIdx.x; i < B6; i += stride) {
        if (i < B0) {
            int r = (int)(i >> 10), c4 = ((int)i & 1023) << 2;
            float4 v = *(const float4*)(W_frame + (size_t)r * FDIM + c4);
            split_w4(Wf2 + (size_t)r * (2 * FDIM) + c4, FDIM, v);
        } else if (i < B2) {
            long long j = i - B0;
            int dec = (j >= 262144LL);
            if (dec) j -= 262144LL;
            int r = (int)(j >> 7), c4 = ((int)j & 127) << 2;
            float4 v = *(const float4*)(W_ih + (size_t)r * 1024 + (dec ? 512 : 0) + c4);
            split_w4((dec ? Wih2d : Wih2e) + (size_t)r * 1024 + c4, 512, v);
        } else if (i < B3) {
            long long j = i - B2;
            int r = (int)(j >> 7), c4 = ((int)j & 127) << 2;
            float4 v = make_float4(0.f, 0.f, 0.f, 0.f);
            if (r < VDIM) v = *(const float4*)(W_out + (size_t)r * HDIM + c4);
            split_w4(Wo2 + (size_t)r * 1024 + c4, 512, v);
        } else if (i < B4) {
            long long j = i - B3;
            int r = (int)(j >> 7), c4 = ((int)j & 127) << 2;   // r = t*64+b
            int t = r >> 6, b = r & 63;
            int id = (t == 0) ? START_ID : labels[b * TSTEPS + (t - 1)];
            float4 v = *(const float4*)(embed + (size_t)id * EDIM + c4);
            split_w4(dece2 + (size_t)r * 1024 + c4, 512, v);
        } else if (i < B5) {
            long long j = i - B4;
            int r = (int)(j >> 7), c4 = ((int)j & 127) << 2;
            float4 v = *(const float4*)(W_hh + (size_t)r * HDIM + c4);
            split_w4(Whh2 + (size_t)r * 1024 + c4, 512, v);
        } else {
            long long j = i - B5;
            int r = (int)(j >> 10), c4 = ((int)j & 1023) << 2;
            float4 v = *(const float4*)(feats + (size_t)r * FDIM + c4);
            split_w4(feats2 + (size_t)r * (2 * FDIM) + c4, FDIM, v);
        }
    }
}

// ---------------- mma.sync bf16 GEMM (embed + xgates), CTA tile 128x256 ----------------
#define STAGE 49152

__device__ __forceinline__ void ld_chunk(uint32_t sbase,
    const __nv_bfloat16* __restrict__ Ab, const __nv_bfloat16* __restrict__ Bb,
    int lda, int ao, int bo, int tid)
{
    const __nv_bfloat16* ap = Ab + ao;
    const __nv_bfloat16* bp = Bb + bo;
#pragma unroll
    for (int u = 0; u < 4; u++) {
        int idx = u * 256 + tid, r = idx >> 3, q = idx & 7;
        cpasync16(sbase + r * 128 + ((q ^ (r & 7)) << 4), ap + (size_t)r * lda + q * 8);
    }
#pragma unroll
    for (int u = 0; u < 8; u++) {
        int idx = u * 256 + tid, r = idx >> 3, q = idx & 7;
        cpasync16(sbase + 16384 + r * 128 + ((q ^ (r & 7)) << 4), bp + (size_t)r * lda + q * 8);
    }
}

__global__ __launch_bounds__(256, 1) void mma_tc(
    const __nv_bfloat16* __restrict__ A, const __nv_bfloat16* __restrict__ Aalt,
    int MsplitBlk, int rowOffAlt,
    const __nv_bfloat16* __restrict__ B, const __nv_bfloat16* __restrict__ Balt,
    const float* __restrict__ bias1, const float* __restrict__ bias2,
    void* __restrict__ Cv, int K, int Nreal, int ldc, int outMode, int outBf)
{
    extern __shared__ char smc[];
    const uint32_t sbase = s2u(smc);
    const int tid = threadIdx.x, lane = tid & 31, wid = tid >> 5;
    const int wn = wid & 3, wm = wid >> 2;
    const int bx = blockIdx.x;
    const bool alt = (Aalt != nullptr) && (bx >= MsplitBlk);
    const int m0 = (alt ? bx - MsplitBlk : bx) * 128;
    const int n0 = blockIdx.y * 256;
    const int rowOff = alt ? rowOffAlt : 0;
    const int lda = 2 * K;
    const int KC = K >> 6, NC = 3 * KC;
    const __nv_bfloat16* Ab = (alt ? Aalt : A) + (size_t)m0 * lda;
    const __nv_bfloat16* Bb = (alt ? Balt : B) + (size_t)n0 * lda;

    float acc[4][8][4];
#pragma unroll
    for (int a = 0; a < 4; a++)
#pragma unroll
        for (int b = 0; b < 8; b++)
#pragma unroll
            for (int d = 0; d < 4; d++) acc[a][b][d] = 0.f;

    ld_chunk(sbase, Ab, Bb, lda, 0, 0, tid);
    asm volatile("cp.async.commit_group;" ::: "memory");

    int segN = 0, kcN = 0;
    for (int c = 0; c < NC; c++) {
        asm volatile("cp.async.wait_group 0;" ::: "memory");
        __syncthreads();

        if (c + 1 < NC) {
            if (++kcN == KC) { kcN = 0; segN++; }
            int ao = ((segN == 2) ? K : 0) + (kcN << 6);
            int bo = ((segN == 1) ? K : 0) + (kcN << 6);
            ld_chunk(sbase + ((c + 1) & 1) * STAGE, Ab, Bb, lda, ao, bo, tid);
            asm volatile("cp.async.commit_group;" ::: "memory");
        }

        const uint32_t sa = sbase + (c & 1) * STAGE;
        const uint32_t sb = sa + 16384;
#pragma unroll
        for (int ks = 0; ks < 4; ks++) {
            uint32_t af[4][4];
#pragma unroll
            for (int mt = 0; mt < 4; mt++) {
                int r = wm * 64 + mt * 16 + (lane & 15);
                int q = 2 * ks + (lane >> 4);
                ldm4(af[mt], sa + r * 128 + ((q ^ (r & 7)) << 4));
            }
            uint32_t bf[4][4];
#pragma unroll
            for (int bp2 = 0; bp2 < 4; bp2++) {
                int r = wn * 64 + (bp2 * 2 + (lane >> 4)) * 8 + (lane & 7);
                int q = 2 * ks + ((lane >> 3) & 1);
                ldm4(bf[bp2], sb + r * 128 + ((q ^ (r & 7)) << 4));
            }
#pragma unroll
            for (int mt = 0; mt < 4; mt++)
#pragma unroll
                for (int nt = 0; nt < 8; nt++)
                    mma16816(acc[mt][nt], af[mt], &bf[nt >> 1][(nt & 1) * 2]);
        }
    }

    const int mb = m0 + wm * 64, nb = n0 + wn * 64;
#pragma unroll
    for (int mt = 0; mt < 4; mt++)
#pragma unroll
        for (int half = 0; half < 2; half++) {
            int r = mb + mt * 16 + (lane >> 2) + half * 8;
            int rr;
            if (outMode == 2) rr = (r % 80) * 64 + (r / 80);
            else              rr = r + rowOff;
#pragma unroll
            for (int nt = 0; nt < 8; nt++) {
                int cb = nb + nt * 8 + (lane & 3) * 2;
                if (cb < Nreal) {
                    float2 bv = *(const float2*)(bias1 + cb);
                    if (bias2) {
                        float2 b2 = *(const float2*)(bias2 + cb);
                        bv.x += b2.x; bv.y += b2.y;
                    }
                    float vx = acc[mt][nt][half * 2 + 0] + bv.x;
                    float vy = acc[mt][nt][half * 2 + 1] + bv.y;
                    if (outBf) {
                        __nv_bfloat16* op = (__nv_bfloat16*)Cv + (size_t)rr * ldc;
                        __nv_bfloat16 h0 = __float2bfloat16(vx), h1 = __float2bfloat16(vy);
                        __nv_bfloat16 l0 = __float2bfloat16(vx - __bfloat162float(h0));
                        __nv_bfloat16 l1 = __float2bfloat16(vy - __bfloat162float(h1));
                        *(__nv_bfloat162*)(op + cb)         = __halves2bfloat162(h0, h1);
                        *(__nv_bfloat162*)(op + Nreal + cb) = __halves2bfloat162(l0, l1);
                    } else {
                        float* op = (float*)Cv + (size_t)rr * ldc;
                        *(float2*)(op + cb) = make_float2(vx, vy);
                    }
                }
            }
        }
}

// ---------------- fused tail: LSTM (CTAs 0-63, R12-fast variant) + gated logits (64-147) ----------------
#define LCTAS 64
#define WCTAS 84
#define NJOBS (40 * 51)
#define SM_B_OFF 131072
#define SM_G_OFF 196608
#define SM_H_OFF (196608 + 64 * 33 * 4)
#define FSMEM    (SM_H_OFF + 2048)

__device__ __forceinline__ float sigf(float x) {
    return __fdividef(1.f, 1.f + __expf(-x));
}
__device__ __forceinline__ float tanhfast(float x) {
    float e = __expf(-2.f * fabsf(x));
    float t = __fdividef(1.f - e, 1.f + e);
    return copysignf(t, x);
}

__device__ __forceinline__ void gsync64()
{
    __syncthreads();
    if (threadIdx.x == 0) {
        unsigned gen;
        asm volatile("ld.relaxed.gpu.global.u32 %0, [%1];" : "=r"(gen) : "l"(&g_bar_gen) : "memory");
        unsigned old;
        asm volatile("atom.acq_rel.gpu.global.add.u32 %0, [%1], 1;"
                     : "=r"(old) : "l"(&g_bar_cnt) : "memory");
        if (old == LCTAS - 1) {
            asm volatile("st.relaxed.gpu.global.u32 [%0], %1;" :: "l"(&g_bar_cnt), "r"(0u) : "memory");
            asm volatile("st.release.gpu.global.u32 [%0], %1;" :: "l"(&g_bar_gen), "r"(gen + 1u) : "memory");
        } else {
            unsigned g;
            do {
                asm volatile("ld.acquire.gpu.global.u32 %0, [%1];" : "=r"(g) : "l"(&g_bar_gen) : "memory");
            } while (g == gen);
        }
    }
    __syncthreads();
}

__global__ __launch_bounds__(256, 1) void fused_tail(
    const __nv_bfloat16* __restrict__ Whh2, const float* __restrict__ xg,
    __nv_bfloat16* __restrict__ hh2, __nv_bfloat16* __restrict__ hb,
    const __nv_bfloat16* __restrict__ Wo2, const float* __restrict__ bout,
    float* __restrict__ out)
{
    extern __shared__ char sml[];
    const uint32_t sb = s2u(sml);
    const int tid = threadIdx.x, lane = tid & 31, wid = tid >> 5;

    unsigned base;
    asm volatile("ld.relaxed.gpu.global.u32 %0, [%1];" : "=r"(base) : "l"(&g_progbase) : "memory");

    if (blockIdx.x < LCTAS) {
        // ================= LSTM role (R12 fast variant) =================
        float* gs = (float*)(sml + SM_G_OFF);
        __nv_bfloat16* hex = (__nv_bfloat16*)(sml + SM_H_OFF);
        const int wm = wid & 3, wn = wid >> 2;
        const int ct = blockIdx.x;

#pragma unroll
        for (int u = 0; u < 16; u++) {
            int idx = u * 256 + tid;
            int n = idx >> 7, rem = idx & 127, pl = rem >> 3, q = rem & 7;
            int h = n >> 2, g = n & 3;
            cpasync16(sb + SM_B_OFF + pl * 4096 + n * 128 + ((q ^ (n & 7)) << 4),
                      Whh2 + (size_t)(g * 512 + ct * 8 + h) * 1024 + pl * 64 + q * 8);
        }
        asm volatile("cp.async.commit_group;" ::: "memory");
        *(uint64_t*)((char*)hb + ct * 2048 + tid * 8) = 0ull;
        asm volatile("cp.async.wait_group 0;" ::: "memory");

        float c0 = 0.f, c1 = 0.f;
        gsync64();

        int cur = 0;
        for (int s = 0; s < NSTEPS; s++) {
            const __nv_bfloat16* hbc = hb + cur * (BATCH * 1024);
#pragma unroll
            for (int u = 0; u < 32; u++) {
                int idx = u * 256 + tid;
                int pl = idx >> 9, r = (idx >> 3) & 63, q = idx & 7;
                cpasync16(sb + pl * 8192 + r * 128 + ((q ^ (r & 7)) << 4),
                          hbc + (size_t)r * 1024 + pl * 64 + q * 8);
            }
            asm volatile("cp.async.commit_group;" ::: "memory");

            float xr[2][4];
#pragma unroll
            for (int p = 0; p < 2; p++) {
                int idx = tid + p * 256;
                int b = idx & 63, hl = idx >> 6;
                const float* xp = xg + (size_t)(s * 64 + b) * GDIM + ct * 8 + hl;
#pragma unroll
                for (int g = 0; g < 4; g++) xr[p][g] = __ldg(xp + g * 512);
            }

            asm volatile("cp.async.wait_group 0;" ::: "memory");
            __syncthreads();

            float acc[2][4];
#pragma unroll
            for (int nt = 0; nt < 2; nt++)
#pragma unroll
                for (int d = 0; d < 4; d++) acc[nt][d] = 0.f;

            // full-unroll 3-seg mainloop (fastest measured)
#pragma unroll
            for (int seg = 0; seg < 3; seg++) {
                const int pa = (seg == 2) ? 8 : 0;
                const int pb = (seg == 1) ? 8 : 0;
#pragma unroll
                for (int kc = 0; kc < 8; kc++) {
                    const uint32_t abase = sb + (pa + kc) * 8192;
                    const uint32_t bbase = sb + SM_B_OFF + (pb + kc) * 4096;
#pragma unroll
                    for (int ks = 0; ks < 4; ks++) {
                        uint32_t af[4], bf[4];
                        {
                            int r = wm * 16 + (lane & 15);
                            int q = 2 * ks + (lane >> 4);
                            ldm4(af, abase + r * 128 + ((q ^ (r & 7)) << 4));
                        }
                        {
                            int r = wn * 16 + (lane >> 4) * 8 + (lane & 7);
                            int q = 2 * ks + ((lane >> 3) & 1);
                            ldm4(bf, bbase + r * 128 + ((q ^ (r & 7)) << 4));
                        }
                        mma16816(acc[0], af, &bf[0]);
                        mma16816(acc[1], af, &bf[2]);
                    }
                }
            }

#pragma unroll
            for (int nt = 0; nt < 2; nt++) {
                int col = wn * 16 + nt * 8 + (lane & 3) * 2;
                int row = wm * 16 + (lane >> 2);
                gs[row * 33 + col]           = acc[nt][0];
                gs[row * 33 + col + 1]       = acc[nt][1];
                gs[(row + 8) * 33 + col]     = acc[nt][2];
                gs[(row + 8) * 33 + col + 1] = acc[nt][3];
            }
            __syncthreads();

#pragma unroll
            for (int p = 0; p < 2; p++) {
                int idx = tid + p * 256;
                int b = idx & 63, hl = idx >> 6;
                float gi = gs[b * 33 + hl * 4 + 0] + xr[p][0];
                float gf = gs[b * 33 + hl * 4 + 1] + xr[p][1];
                float gg = gs[b * 33 + hl * 4 + 2] + xr[p][2];
                float go = gs[b * 33 + hl * 4 + 3] + xr[p][3];
                float iv = sigf(gi), fv = sigf(gf), gv = tanhfast(gg), ov = sigf(go);
                float cc = (p ? c1 : c0);
                cc = fv * cc + iv * gv;
                if (p) c1 = cc; else c0 = cc;
                float hv = ov * tanhfast(cc);
                __nv_bfloat16 hbv = __float2bfloat16(hv);
                __nv_bfloat16 lbv = __float2bfloat16(hv - __bfloat162float(hbv));
                hex[b * 8 + hl]       = hbv;
                hex[512 + b * 8 + hl] = lbv;
            }
            __syncthreads();

            if (tid < 128) {
                int half = tid >> 6, b = tid & 63;
                uint4 v = *(const uint4*)(hex + half * 512 + b * 8);
                __nv_bfloat16* hbn = hb + (cur ^ 1) * (BATCH * 1024);
                *(uint4*)(hbn + (size_t)b * 1024 + half * 512 + ct * 8) = v;
                if (s >= TSTEPS) {
                    int t = s - TSTEPS;
                    *(uint4*)(hh2 + (size_t)(t * 64 + b) * 1024 + half * 512 + ct * 8) = v;
                }
            }

            gsync64();
            if (ct == 0 && tid == 0) {
                unsigned pv = base + (unsigned)(s + 1);
                asm volatile("st.release.gpu.global.u32 [%0], %1;" :: "l"(&g_prog), "r"(pv) : "memory");
            }
            cur ^= 1;
        }
    } else {
        // ================= logits worker role (gated, throttled) =================
        const uint32_t sbase = sb;
        const int wn = wid & 3, wm = wid >> 2;
        const int cta = blockIdx.x - LCTAS;
        const int lda = 1024;   // 2*K, K=512

        for (int j = cta; j < NJOBS; j += WCTAS) {
            int mblk = j % 40, nblk = j / 40;
            int m0 = mblk * 128, n0 = nblk * 256;
            if (tid == 0) {
                unsigned tgt = base + (unsigned)(82 + 2 * mblk);
                for (;;) {
                    unsigned g;
                    asm volatile("ld.acquire.gpu.global.u32 %0, [%1];" : "=r"(g) : "l"(&g_prog) : "memory");
                    if ((int)(g - tgt) >= 0) break;
                    __nanosleep(256);
                }
            }
            __syncthreads();

            const __nv_bfloat16* Ab = hh2 + (size_t)m0 * lda;
            const __nv_bfloat16* Bb = Wo2 + (size_t)n0 * lda;

            float acc[4][8][4];
#pragma unroll
            for (int a = 0; a < 4; a++)
#pragma unroll
                for (int b = 0; b < 8; b++)
#pragma unroll
                    for (int d = 0; d < 4; d++) acc[a][b][d] = 0.f;

            ld_chunk(sbase, Ab, Bb, lda, 0, 0, tid);
            asm volatile("cp.async.commit_group;" ::: "memory");

            int segN = 0, kcN = 0;
            for (int c = 0; c < 24; c++) {
                asm volatile("cp.async.wait_group 0;" ::: "memory");
                __syncthreads();
                if (c + 1 < 24) {
                    if (++kcN == 8) { kcN = 0; segN++; }
                    int ao = ((segN == 2) ? 512 : 0) + (kcN << 6);
                    int bo = ((segN == 1) ? 512 : 0) + (kcN << 6);
                    ld_chunk(sbase + ((c + 1) & 1) * STAGE, Ab, Bb, lda, ao, bo, tid);
                    asm volatile("cp.async.commit_group;" ::: "memory");
                }
                const uint32_t sa = sbase + (c & 1) * STAGE;
                const uint32_t sB = sa + 16384;
#pragma unroll
                for (int ks = 0; ks < 4; ks++) {
                    uint32_t af[4][4];
#pragma unroll
                    for (int mt = 0; mt < 4; mt++) {
                        int r = wm * 64 + mt * 16 + (lane & 15);
                        int q = 2 * ks + (lane >> 4);
                        ldm4(af[mt], sa + r * 128 + ((q ^ (r & 7)) << 4));
                    }
                    uint32_t bf[4][4];
#pragma unroll
                    for (int bp2 = 0; bp2 < 4; bp2++) {
                        int r = wn * 64 + (bp2 * 2 + (lane >> 4)) * 8 + (lane & 7);
                        int q = 2 * ks + ((lane >> 3) & 1);
                        ldm4(bf[bp2], sB + r * 128 + ((q ^ (r & 7)) << 4));
                    }
#pragma unroll
                    for (int mt = 0; mt < 4; mt++)
#pragma unroll
                        for (int nt = 0; nt < 8; nt++)
                            mma16816(acc[mt][nt], af[mt], &bf[nt >> 1][(nt & 1) * 2]);
                }
            }

            const int mb = m0 + wm * 64, nb = n0 + wn * 64;
#pragma unroll
            for (int mt = 0; mt < 4; mt++)
#pragma unroll
                for (int half = 0; half < 2; half++) {
                    int r = mb + mt * 16 + (lane >> 2) + half * 8;
                    int rr = (r & 63) * 80 + (r >> 6);   // t-major -> b*80+t
                    float* op = out + (size_t)rr * VDIM;
#pragma unroll
                    for (int nt = 0; nt < 8; nt++) {
                        int cb = nb + nt * 8 + (lane & 3) * 2;
                        if (cb < VDIM) {
                            float2 bv = *(const float2*)(bout + cb);
                            *(float2*)(op + cb) = make_float2(
                                acc[mt][nt][half * 2 + 0] + bv.x,
                                acc[mt][nt][half * 2 + 1] + bv.y);
                        }
                    }
                }
            __syncthreads();
        }
    }
}

// ---------------- launch ----------------
extern "C" void kernel_launch(void* const* d_in, const int* in_sizes, int n_in,
                              void* d_out, int out_size)
{
    const float* feats   = (const float*)d_in[0];
    const int*   labels  = (const int*)  d_in[1];
    const float* W_frame = (const float*)d_in[2];
    const float* b_frame = (const float*)d_in[3];
    const float* embed   = (const float*)d_in[4];
    const float* W_ih    = (const float*)d_in[5];
    const float* W_hh    = (const float*)d_in[6];
    const float* b_ih    = (const float*)d_in[7];
    const float* b_hh    = (const float*)d_in[8];
    const float* W_out   = (const float*)d_in[9];
    const float* b_out   = (const float*)d_in[10];
    float* out = (float*)d_out;

    float* p_xgate;
    __nv_bfloat16 *p_feats2, *p_Wf2, *p_emb2, *p_Wih2e, *p_Wih2d, *p_dece2, *p_Whh2, *p_hh2, *p_Wo2, *p_hb;
    cudaGetSymbolAddress((void**)&p_xgate,  g_xgate);
    cudaGetSymbolAddress((void**)&p_feats2, g_feats2);
    cudaGetSymbolAddress((void**)&p_Wf2,    g_Wf2);
    cudaGetSymbolAddress((void**)&p_emb2,   g_emb2);
    cudaGetSymbolAddress((void**)&p_Wih2e,  g_Wih2e);
    cudaGetSymbolAddress((void**)&p_Wih2d,  g_Wih2d);
    cudaGetSymbolAddress((void**)&p_dece2,  g_dece2);
    cudaGetSymbolAddress((void**)&p_Whh2,   g_Whh2);
    cudaGetSymbolAddress((void**)&p_hh2,    g_hh2);
    cudaGetSymbolAddress((void**)&p_Wo2,    g_Wo2);
    cudaGetSymbolAddress((void**)&p_hb,     g_hbufb);

    cudaFuncSetAttribute(fused_tail, cudaFuncAttributeMaxDynamicSharedMemorySize, FSMEM);
    const int smem_tc = 2 * STAGE;
    cudaFuncSetAttribute(mma_tc, cudaFuncAttributeMaxDynamicSharedMemorySize, smem_tc);

    // [0] prep (snapshots g_progbase)
    prep_all<<<1480, 256>>>(labels, embed, W_frame, W_ih, W_out, W_hh, feats,
                            p_Wf2, p_Wih2e, p_Wih2d, p_Wo2, p_dece2, p_Whh2, p_feats2);
    // [1] frame embedding -> g_emb2 (bf16 dual, t-major rows), K=4096
    {
        dim3 grid(MROWS / 128, EDIM / 256);
        mma_tc<<<grid, 256, smem_tc>>>(p_feats2, nullptr, 1 << 30, 0, p_Wf2, nullptr,
                                       b_frame, nullptr, p_emb2, FDIM, EDIM, 2 * EDIM, 2, 1);
    }
    // [2] both x-gate GEMMs fused, K=512
    {
        dim3 grid(2 * (MROWS / 128), GDIM / 256);
        mma_tc<<<grid, 256, smem_tc>>>(p_emb2, p_dece2, MROWS / 128, MROWS,
                                       p_Wih2e, p_Wih2d, b_ih, b_hh,
                                       p_xgate, EDIM, GDIM, GDIM, 0, 0);
    }
    // [3] fused recurrence + overlapped logits  <-- profiled launch
    fused_tail<<<LCTAS + WCTAS, 256, FSMEM>>>(p_Whh2, p_xgate, p_hh2, p_hb,
                                              p_Wo2, b_out, out);
}

// round 15
// speedup vs baseline: 1.1594x; 1.1499x over previous
#include <cuda_runtime.h>
#include <cuda_bf16.h>
#include <math.h>
#include <stdint.h>

#define TSTEPS 80
#define BATCH  64
#define FDIM   4096
#define EDIM   512
#define HDIM   512
#define VDIM   13000
#define VPAD   13056
#define GDIM   2048
#define NSTEPS 160
#define MROWS  5120
#define START_ID 1

// ---------------- scratch ----------------
__device__ __align__(16) __nv_bfloat16 g_feats2[(size_t)MROWS * 2 * FDIM];   // [hi|lo]
__device__ __align__(16) __nv_bfloat16 g_Wf2   [(size_t)EDIM  * 2 * FDIM];
__device__ __align__(16) __nv_bfloat16 g_emb2  [(size_t)MROWS * 2 * EDIM];   // t-major rows
__device__ __align__(16) __nv_bfloat16 g_Wih2e [(size_t)GDIM  * 2 * EDIM];
__device__ __align__(16) __nv_bfloat16 g_Wih2d [(size_t)GDIM  * 2 * EDIM];
__device__ __align__(16) __nv_bfloat16 g_dece2 [(size_t)MROWS * 2 * EDIM];   // t-major rows
__device__ __align__(16) __nv_bfloat16 g_Whh2  [(size_t)GDIM  * 2 * HDIM];   // [hi|lo]
__device__ __align__(16) float         g_xgate [(size_t)NSTEPS * BATCH * GDIM]; // [s*64+b][2048]
__device__ __align__(16) __nv_bfloat16 g_hh2   [(size_t)MROWS * 2 * HDIM];   // t-major rows
__device__ __align__(16) __nv_bfloat16 g_Wo2   [(size_t)VPAD  * 2 * HDIM];
__device__ __align__(16) __nv_bfloat16 g_hbufb [2][BATCH * 1024];            // h ping-pong bf16 [hi|lo]
__device__ __align__(256) unsigned g_bar_cnt;
__device__ __align__(256) unsigned g_bar_gen;

// ---------------- generic-PTX helpers ----------------
__device__ __forceinline__ uint32_t s2u(const void* p) {
    uint32_t a;
    asm("{ .reg .u64 t; cvta.to.shared.u64 t, %1; cvt.u32.u64 %0, t; }" : "=r"(a) : "l"(p));
    return a;
}
__device__ __forceinline__ void cpasync16(uint32_t dst, const void* src) {
    asm volatile("cp.async.cg.shared.global [%0], [%1], 16;" :: "r"(dst), "l"(src));
}
__device__ __forceinline__ void ldm4(uint32_t* d, uint32_t addr) {
    asm volatile("ldmatrix.sync.aligned.m8n8.x4.shared.b16 {%0,%1,%2,%3}, [%4];"
        : "=r"(d[0]), "=r"(d[1]), "=r"(d[2]), "=r"(d[3]) : "r"(addr));
}
__device__ __forceinline__ void mma16816(float* c, const uint32_t* a, const uint32_t* b) {
    asm volatile("mma.sync.aligned.m16n8k16.row.col.f32.bf16.bf16.f32 "
        "{%0,%1,%2,%3}, {%4,%5,%6,%7}, {%8,%9}, {%0,%1,%2,%3};"
        : "+f"(c[0]), "+f"(c[1]), "+f"(c[2]), "+f"(c[3])
        : "r"(a[0]), "r"(a[1]), "r"(a[2]), "r"(a[3]), "r"(b[0]), "r"(b[1]));
}
__device__ __forceinline__ void split_w4(__nv_bfloat16* dst, int K, float4 v) {
    float vv[4] = {v.x, v.y, v.z, v.w};
    __nv_bfloat16 hi[4], lo[4];
#pragma unroll
    for (int j = 0; j < 4; j++) {
        hi[j] = __float2bfloat16(vv[j]);
        lo[j] = __float2bfloat16(vv[j] - __bfloat162float(hi[j]));
    }
    *(uint64_t*)(dst)     = *(const uint64_t*)hi;
    *(uint64_t*)(dst + K) = *(const uint64_t*)lo;
}

// ---------------- prep ----------------
#define B0 524288LL
#define B1 (B0 + 262144LL)
#define B2 (B1 + 262144LL)
#define B3 (B2 + 1671168LL)
#define B4 (B3 + 655360LL)
#define B5 (B4 + 262144LL)
#define B6 (B5 + 5242880LL)

__global__ void prep_all(const int* __restrict__ labels, const float* __restrict__ embed,
                         const float* __restrict__ W_frame, const float* __restrict__ W_ih,
                         const float* __restrict__ W_out, const float* __restrict__ W_hh,
                         const float* __restrict__ feats,
                         __nv_bfloat16* __restrict__ Wf2,
                         __nv_bfloat16* __restrict__ Wih2e, __nv_bfloat16* __restrict__ Wih2d,
                         __nv_bfloat16* __restrict__ Wo2, __nv_bfloat16* __restrict__ dece2,
                         __nv_bfloat16* __restrict__ Whh2, __nv_bfloat16* __restrict__ feats2)
{
    const long long stride = (long long)gridDim.x * blockDim.x;
    for (long long i = (long long)blockIdx.x * blockDim.x + threadIdx.x; i < B6; i += stride) {
        if (i < B0) {
            int r = (int)(i >> 10), c4 = ((int)i & 1023) << 2;
            float4 v = *(const float4*)(W_frame + (size_t)r * FDIM + c4);
            split_w4(Wf2 + (size_t)r * (2 * FDIM) + c4, FDIM, v);
        } else if (i < B2) {
            long long j = i - B0;
            int dec = (j >= 262144LL);
            if (dec) j -= 262144LL;
            int r = (int)(j >> 7), c4 = ((int)j & 127) << 2;
            float4 v = *(const float4*)(W_ih + (size_t)r * 1024 + (dec ? 512 : 0) + c4);
            split_w4((dec ? Wih2d : Wih2e) + (size_t)r * 1024 + c4, 512, v);
        } else if (i < B3) {
            long long j = i - B2;
            int r = (int)(j >> 7), c4 = ((int)j & 127) << 2;
            float4 v = make_float4(0.f, 0.f, 0.f, 0.f);
            if (r < VDIM) v = *(const float4*)(W_out + (size_t)r * HDIM + c4);
            split_w4(Wo2 + (size_t)r * 1024 + c4, 512, v);
        } else if (i < B4) {
            long long j = i - B3;
            int r = (int)(j >> 7), c4 = ((int)j & 127) << 2;   // r = t*64+b
            int t = r >> 6, b = r & 63;
            int id = (t == 0) ? START_ID : labels[b * TSTEPS + (t - 1)];
            float4 v = *(const float4*)(embed + (size_t)id * EDIM + c4);
            split_w4(dece2 + (size_t)r * 1024 + c4, 512, v);
        } else if (i < B5) {
            long long j = i - B4;
            int r = (int)(j >> 7), c4 = ((int)j & 127) << 2;
            float4 v = *(const float4*)(W_hh + (size_t)r * HDIM + c4);
            split_w4(Whh2 + (size_t)r * 1024 + c4, 512, v);
        } else {
            long long j = i - B5;
            int r = (int)(j >> 10), c4 = ((int)j & 1023) << 2;
            float4 v = *(const float4*)(feats + (size_t)r * FDIM + c4);
            split_w4(feats2 + (size_t)r * (2 * FDIM) + c4, FDIM, v);
        }
    }
}

// ---------------- mma.sync bf16 GEMM, 2-seg exact-split, CTA tile 128x256 ----------------
#define STAGE 49152

__device__ __forceinline__ void ld_chunk(uint32_t sbase,
    const __nv_bfloat16* __restrict__ Ab, const __nv_bfloat16* __restrict__ Bb,
    int lda, int ao, int bo, int tid)
{
    const __nv_bfloat16* ap = Ab + ao;
    const __nv_bfloat16* bp = Bb + bo;
#pragma unroll
    for (int u = 0; u < 4; u++) {
        int idx = u * 256 + tid, r = idx >> 3, q = idx & 7;
        cpasync16(sbase + r * 128 + ((q ^ (r & 7)) << 4), ap + (size_t)r * lda + q * 8);
    }
#pragma unroll
    for (int u = 0; u < 8; u++) {
        int idx = u * 256 + tid, r = idx >> 3, q = idx & 7;
        cpasync16(sbase + 16384 + r * 128 + ((q ^ (r & 7)) << 4), bp + (size_t)r * lda + q * 8);
    }
}

__global__ __launch_bounds__(256, 1) void mma_tc(
    const __nv_bfloat16* __restrict__ A, const __nv_bfloat16* __restrict__ Aalt,
    int MsplitBlk, int rowOffAlt,
    const __nv_bfloat16* __restrict__ B, const __nv_bfloat16* __restrict__ Balt,
    const float* __restrict__ bias1, const float* __restrict__ bias2,
    void* __restrict__ Cv, int K, int Nreal, int ldc, int outMode, int outBf)
{
    extern __shared__ char smc[];
    const uint32_t sbase = s2u(smc);
    const int tid = threadIdx.x, lane = tid & 31, wid = tid >> 5;
    const int wn = wid & 3, wm = wid >> 2;
    const int bx = blockIdx.x;
    const bool alt = (Aalt != nullptr) && (bx >= MsplitBlk);
    const int m0 = (alt ? bx - MsplitBlk : bx) * 128;
    const int n0 = blockIdx.y * 256;
    const int rowOff = alt ? rowOffAlt : 0;
    const int lda = 2 * K;
    const int KC = K >> 6, NC = 3 * KC;
    const __nv_bfloat16* Ab = (alt ? Aalt : A) + (size_t)m0 * lda;
    const __nv_bfloat16* Bb = (alt ? Balt : B) + (size_t)n0 * lda;

    float acc[4][8][4];
#pragma unroll
    for (int a = 0; a < 4; a++)
#pragma unroll
        for (int b = 0; b < 8; b++)
#pragma unroll
            for (int d = 0; d < 4; d++) acc[a][b][d] = 0.f;

    ld_chunk(sbase, Ab, Bb, lda, 0, 0, tid);
    asm volatile("cp.async.commit_group;" ::: "memory");

    int segN = 0, kcN = 0;
    for (int c = 0; c < NC; c++) {
        asm volatile("cp.async.wait_group 0;" ::: "memory");
        __syncthreads();

        if (c + 1 < NC) {
            if (++kcN == KC) { kcN = 0; segN++; }
            int ao = ((segN == 2) ? K : 0) + (kcN << 6);
            int bo = ((segN == 1) ? K : 0) + (kcN << 6);
            ld_chunk(sbase + ((c + 1) & 1) * STAGE, Ab, Bb, lda, ao, bo, tid);
            asm volatile("cp.async.commit_group;" ::: "memory");
        }

        const uint32_t sa = sbase + (c & 1) * STAGE;
        const uint32_t sb = sa + 16384;
#pragma unroll
        for (int ks = 0; ks < 4; ks++) {
            uint32_t af[4][4];
#pragma unroll
            for (int mt = 0; mt < 4; mt++) {
                int r = wm * 64 + mt * 16 + (lane & 15);
                int q = 2 * ks + (lane >> 4);
                ldm4(af[mt], sa + r * 128 + ((q ^ (r & 7)) << 4));
            }
            uint32_t bf[4][4];
#pragma unroll
            for (int bp2 = 0; bp2 < 4; bp2++) {
                int r = wn * 64 + (bp2 * 2 + (lane >> 4)) * 8 + (lane & 7);
                int q = 2 * ks + ((lane >> 3) & 1);
                ldm4(bf[bp2], sb + r * 128 + ((q ^ (r & 7)) << 4));
            }
#pragma unroll
            for (int mt = 0; mt < 4; mt++)
#pragma unroll
                for (int nt = 0; nt < 8; nt++)
                    mma16816(acc[mt][nt], af[mt], &bf[nt >> 1][(nt & 1) * 2]);
        }
    }

    const int mb = m0 + wm * 64, nb = n0 + wn * 64;
#pragma unroll
    for (int mt = 0; mt < 4; mt++)
#pragma unroll
        for (int half = 0; half < 2; half++) {
            int r = mb + mt * 16 + (lane >> 2) + half * 8;
            int rr;
            if (outMode == 1)      rr = (r & 63) * 80 + (r >> 6);   // t-major -> b*80+t
            else if (outMode == 2) rr = (r % 80) * 64 + (r / 80);   // b-major -> t*64+b
            else                   rr = r + rowOff;
#pragma unroll
            for (int nt = 0; nt < 8; nt++) {
                int cb = nb + nt * 8 + (lane & 3) * 2;
                if (cb < Nreal) {
                    float2 bv = *(const float2*)(bias1 + cb);
                    if (bias2) {
                        float2 b2 = *(const float2*)(bias2 + cb);
                        bv.x += b2.x; bv.y += b2.y;
                    }
                    float vx = acc[mt][nt][half * 2 + 0] + bv.x;
                    float vy = acc[mt][nt][half * 2 + 1] + bv.y;
                    if (outBf) {
                        __nv_bfloat16* op = (__nv_bfloat16*)Cv + (size_t)rr * ldc;
                        __nv_bfloat16 h0 = __float2bfloat16(vx), h1 = __float2bfloat16(vy);
                        __nv_bfloat16 l0 = __float2bfloat16(vx - __bfloat162float(h0));
                        __nv_bfloat16 l1 = __float2bfloat16(vy - __bfloat162float(h1));
                        *(__nv_bfloat162*)(op + cb)         = __halves2bfloat162(h0, h1);
                        *(__nv_bfloat162*)(op + Nreal + cb) = __halves2bfloat162(l0, l1);
                    } else {
                        float* op = (float*)Cv + (size_t)rr * ldc;
                        *(float2*)(op + cb) = make_float2(vx, vy);
                    }
                }
            }
        }
}

// ---------------- persistent LSTM on tensor cores (fastest measured variant) ----------------
#define LCTAS 64
#define SM_B_OFF 131072
#define SM_G_OFF 196608
#define SM_H_OFF (196608 + 64 * 33 * 4)
#define LSMEM    (SM_H_OFF + 2048)

__device__ __forceinline__ float sigf(float x) {
    return __fdividef(1.f, 1.f + __expf(-x));
}
__device__ __forceinline__ float tanhfast(float x) {
    float e = __expf(-2.f * fabsf(x));
    float t = __fdividef(1.f - e, 1.f + e);
    return copysignf(t, x);
}

__device__ __forceinline__ void gsync64()
{
    __syncthreads();
    if (threadIdx.x == 0) {
        unsigned gen;
        asm volatile("ld.relaxed.gpu.global.u32 %0, [%1];" : "=r"(gen) : "l"(&g_bar_gen) : "memory");
        unsigned old;
        asm volatile("atom.acq_rel.gpu.global.add.u32 %0, [%1], 1;"
                     : "=r"(old) : "l"(&g_bar_cnt) : "memory");
        if (old == LCTAS - 1) {
            asm volatile("st.relaxed.gpu.global.u32 [%0], %1;" :: "l"(&g_bar_cnt), "r"(0u) : "memory");
            asm volatile("st.release.gpu.global.u32 [%0], %1;" :: "l"(&g_bar_gen), "r"(gen + 1u) : "memory");
        } else {
            unsigned g;
            do {
                asm volatile("ld.acquire.gpu.global.u32 %0, [%1];" : "=r"(g) : "l"(&g_bar_gen) : "memory");
            } while (g == gen);
        }
    }
    __syncthreads();
}

__global__ __launch_bounds__(256, 1) void lstm_tc(
    const __nv_bfloat16* __restrict__ Whh2, const float* __restrict__ xg,
    __nv_bfloat16* __restrict__ hh2, __nv_bfloat16* __restrict__ hb)
{
    extern __shared__ char sml[];
    const uint32_t sb = s2u(sml);
    float* gs = (float*)(sml + SM_G_OFF);
    __nv_bfloat16* hex = (__nv_bfloat16*)(sml + SM_H_OFF);
    const int tid = threadIdx.x, lane = tid & 31, wid = tid >> 5;
    const int wm = wid & 3, wn = wid >> 2;     // 4 m-tiles(16) x 2 n-tiles(16)
    const int ct = blockIdx.x;

    // W tile: smem row n = h*4+g <- global row g*512 + ct*8 + h
#pragma unroll
    for (int u = 0; u < 16; u++) {
        int idx = u * 256 + tid;
        int n = idx >> 7, rem = idx & 127, pl = rem >> 3, q = rem & 7;
        int h = n >> 2, g = n & 3;
        cpasync16(sb + SM_B_OFF + pl * 4096 + n * 128 + ((q ^ (n & 7)) << 4),
                  Whh2 + (size_t)(g * 512 + ct * 8 + h) * 1024 + pl * 64 + q * 8);
    }
    asm volatile("cp.async.commit_group;" ::: "memory");
    *(uint64_t*)((char*)hb + ct * 2048 + tid * 8) = 0ull;   // zero hbuf[0]
    asm volatile("cp.async.wait_group 0;" ::: "memory");

    float c0 = 0.f, c1 = 0.f;
    gsync64();

    int cur = 0;
    for (int s = 0; s < NSTEPS; s++) {
        const __nv_bfloat16* hbc = hb + cur * (BATCH * 1024);
#pragma unroll
        for (int u = 0; u < 32; u++) {
            int idx = u * 256 + tid;
            int pl = idx >> 9, r = (idx >> 3) & 63, q = idx & 7;
            cpasync16(sb + pl * 8192 + r * 128 + ((q ^ (r & 7)) << 4),
                      hbc + (size_t)r * 1024 + pl * 64 + q * 8);
        }
        asm volatile("cp.async.commit_group;" ::: "memory");

        float xr[2][4];
#pragma unroll
        for (int p = 0; p < 2; p++) {
            int idx = tid + p * 256;
            int b = idx & 63, hl = idx >> 6;
            const float* xp = xg + (size_t)(s * 64 + b) * GDIM + ct * 8 + hl;
#pragma unroll
            for (int g = 0; g < 4; g++) xr[p][g] = __ldg(xp + g * 512);
        }

        asm volatile("cp.async.wait_group 0;" ::: "memory");
        __syncthreads();

        float acc[2][4];
#pragma unroll
        for (int nt = 0; nt < 2; nt++)
#pragma unroll
            for (int d = 0; d < 4; d++) acc[nt][d] = 0.f;

        // full-unroll 3-seg mainloop (fastest measured)
#pragma unroll
        for (int seg = 0; seg < 3; seg++) {
            const int pa = (seg == 2) ? 8 : 0;
            const int pb = (seg == 1) ? 8 : 0;
#pragma unroll
            for (int kc = 0; kc < 8; kc++) {
                const uint32_t abase = sb + (pa + kc) * 8192;
                const uint32_t bbase = sb + SM_B_OFF + (pb + kc) * 4096;
#pragma unroll
                for (int ks = 0; ks < 4; ks++) {
                    uint32_t af[4], bf[4];
                    {
                        int r = wm * 16 + (lane & 15);
                        int q = 2 * ks + (lane >> 4);
                        ldm4(af, abase + r * 128 + ((q ^ (r & 7)) << 4));
                    }
                    {
                        int r = wn * 16 + (lane >> 4) * 8 + (lane & 7);
                        int q = 2 * ks + ((lane >> 3) & 1);
                        ldm4(bf, bbase + r * 128 + ((q ^ (r & 7)) << 4));
                    }
                    mma16816(acc[0], af, &bf[0]);
                    mma16816(acc[1], af, &bf[2]);
                }
            }
        }

#pragma unroll
        for (int nt = 0; nt < 2; nt++) {
            int col = wn * 16 + nt * 8 + (lane & 3) * 2;
            int row = wm * 16 + (lane >> 2);
            gs[row * 33 + col]           = acc[nt][0];
            gs[row * 33 + col + 1]       = acc[nt][1];
            gs[(row + 8) * 33 + col]     = acc[nt][2];
            gs[(row + 8) * 33 + col + 1] = acc[nt][3];
        }
        __syncthreads();

#pragma unroll
        for (int p = 0; p < 2; p++) {
            int idx = tid + p * 256;
            int b = idx & 63, hl = idx >> 6;
            float gi = gs[b * 33 + hl * 4 + 0] + xr[p][0];
            float gf = gs[b * 33 + hl * 4 + 1] + xr[p][1];
            float gg = gs[b * 33 + hl * 4 + 2] + xr[p][2];
            float go = gs[b * 33 + hl * 4 + 3] + xr[p][3];
            float iv = sigf(gi), fv = sigf(gf), gv = tanhfast(gg), ov = sigf(go);
            float cc = (p ? c1 : c0);
            cc = fv * cc + iv * gv;
            if (p) c1 = cc; else c0 = cc;
            float hv = ov * tanhfast(cc);
            __nv_bfloat16 hbv = __float2bfloat16(hv);
            __nv_bfloat16 lbv = __float2bfloat16(hv - __bfloat162float(hbv));
            hex[b * 8 + hl]       = hbv;
            hex[512 + b * 8 + hl] = lbv;
        }
        __syncthreads();

        // coalesced 16B global stores
        if (tid < 128) {
            int half = tid >> 6, b = tid & 63;
            uint4 v = *(const uint4*)(hex + half * 512 + b * 8);
            __nv_bfloat16* hbn = hb + (cur ^ 1) * (BATCH * 1024);
            *(uint4*)(hbn + (size_t)b * 1024 + half * 512 + ct * 8) = v;
            if (s >= TSTEPS) {
                int t = s - TSTEPS;
                *(uint4*)(hh2 + (size_t)(t * 64 + b) * 1024 + half * 512 + ct * 8) = v;
            }
        }

        gsync64();
        cur ^= 1;
    }
}

// ---------------- launch ----------------
extern "C" void kernel_launch(void* const* d_in, const int* in_sizes, int n_in,
                              void* d_out, int out_size)
{
    const float* feats   = (const float*)d_in[0];
    const int*   labels  = (const int*)  d_in[1];
    const float* W_frame = (const float*)d_in[2];
    const float* b_frame = (const float*)d_in[3];
    const float* embed   = (const float*)d_in[4];
    const float* W_ih    = (const float*)d_in[5];
    const float* W_hh    = (const float*)d_in[6];
    const float* b_ih    = (const float*)d_in[7];
    const float* b_hh    = (const float*)d_in[8];
    const float* W_out   = (const float*)d_in[9];
    const float* b_out   = (const float*)d_in[10];
    float* out = (float*)d_out;

    float* p_xgate;
    __nv_bfloat16 *p_feats2, *p_Wf2, *p_emb2, *p_Wih2e, *p_Wih2d, *p_dece2, *p_Whh2, *p_hh2, *p_Wo2, *p_hb;
    cudaGetSymbolAddress((void**)&p_xgate,  g_xgate);
    cudaGetSymbolAddress((void**)&p_feats2, g_feats2);
    cudaGetSymbolAddress((void**)&p_Wf2,    g_Wf2);
    cudaGetSymbolAddress((void**)&p_emb2,   g_emb2);
    cudaGetSymbolAddress((void**)&p_Wih2e,  g_Wih2e);
    cudaGetSymbolAddress((void**)&p_Wih2d,  g_Wih2d);
    cudaGetSymbolAddress((void**)&p_dece2,  g_dece2);
    cudaGetSymbolAddress((void**)&p_Whh2,   g_Whh2);
    cudaGetSymbolAddress((void**)&p_hh2,    g_hh2);
    cudaGetSymbolAddress((void**)&p_Wo2,    g_Wo2);
    cudaGetSymbolAddress((void**)&p_hb,     g_hbufb);

    cudaFuncSetAttribute(lstm_tc, cudaFuncAttributeMaxDynamicSharedMemorySize, LSMEM);
    const int smem_tc = 2 * STAGE;
    cudaFuncSetAttribute(mma_tc, cudaFuncAttributeMaxDynamicSharedMemorySize, smem_tc);

    // [0] prep
    prep_all<<<1480, 256>>>(labels, embed, W_frame, W_ih, W_out, W_hh, feats,
                            p_Wf2, p_Wih2e, p_Wih2d, p_Wo2, p_dece2, p_Whh2, p_feats2);
    // [1] frame embedding -> g_emb2 (bf16 dual, t-major rows), K=4096
    {
        dim3 grid(MROWS / 128, EDIM / 256);
        mma_tc<<<grid, 256, smem_tc>>>(p_feats2, nullptr, 1 << 30, 0, p_Wf2, nullptr,
                                       b_frame, nullptr, p_emb2, FDIM, EDIM, 2 * EDIM, 2, 1);
    }
    // [2] both x-gate GEMMs fused (enc m-blocks 0-39, dec 40-79), K=512
    {
        dim3 grid(2 * (MROWS / 128), GDIM / 256);
        mma_tc<<<grid, 256, smem_tc>>>(p_emb2, p_dece2, MROWS / 128, MROWS,
                                       p_Wih2e, p_Wih2d, b_ih, b_hh,
                                       p_xgate, EDIM, GDIM, GDIM, 0, 0);
    }
    // [3] recurrence  <-- profiled launch
    lstm_tc<<<LCTAS, 256, LSMEM>>>(p_Whh2, p_xgate, p_hh2, p_hb);
    // [4] logits, K=512, t-major -> b-major remap
    {
        dim3 grid(MROWS / 128, VPAD / 256);
        mma_tc<<<grid, 256, smem_tc>>>(p_hh2, nullptr, 1 << 30, 0, p_Wo2, nullptr,
                                       b_out, nullptr, out, HDIM, VDIM, VDIM, 1, 0);
    }
}

// round 16
// speedup vs baseline: 1.2119x; 1.0453x over previous
#include <cuda_runtime.h>
#include <cuda_bf16.h>
#include <math.h>
#include <stdint.h>

#define TSTEPS 80
#define BATCH  64
#define FDIM   4096
#define EDIM   512
#define HDIM   512
#define VDIM   13000
#define VPAD   13056
#define GDIM   2048
#define NSTEPS 160
#define MROWS  5120
#define START_ID 1

// ---------------- scratch ----------------
__device__ __align__(16) __nv_bfloat16 g_feats2[(size_t)MROWS * 2 * FDIM];   // [hi|lo]
__device__ __align__(16) __nv_bfloat16 g_Wf2   [(size_t)EDIM  * 2 * FDIM];
__device__ __align__(16) __nv_bfloat16 g_emb2  [(size_t)MROWS * 2 * EDIM];   // t-major rows
__device__ __align__(16) __nv_bfloat16 g_Wih2e [(size_t)GDIM  * 2 * EDIM];
__device__ __align__(16) __nv_bfloat16 g_Wih2d [(size_t)GDIM  * 2 * EDIM];
__device__ __align__(16) __nv_bfloat16 g_dece2 [(size_t)MROWS * 2 * EDIM];   // t-major rows
__device__ __align__(16) __nv_bfloat16 g_Whh2  [(size_t)GDIM  * 2 * HDIM];   // [hi|lo]
__device__ __align__(16) float         g_xgate [(size_t)NSTEPS * BATCH * GDIM]; // [s*64+b][2048]
__device__ __align__(16) __nv_bfloat16 g_hh2   [(size_t)MROWS * 2 * HDIM];   // t-major rows
__device__ __align__(16) __nv_bfloat16 g_Wo2   [(size_t)VPAD  * 2 * HDIM];
__device__ __align__(16) __nv_bfloat16 g_hbufb [2][BATCH * 1024];            // h ping-pong bf16 [hi|lo]
// barrier state: tree (8 groups x 8), each counter on a private 256B line
__device__ __align__(256) unsigned g_grp[8 * 64];
__device__ __align__(256) unsigned g_cnt_top;
__device__ __align__(256) unsigned g_bar_gen;

// ---------------- generic-PTX helpers ----------------
__device__ __forceinline__ uint32_t s2u(const void* p) {
    uint32_t a;
    asm("{ .reg .u64 t; cvta.to.shared.u64 t, %1; cvt.u32.u64 %0, t; }" : "=r"(a) : "l"(p));
    return a;
}
__device__ __forceinline__ void cpasync16(uint32_t dst, const void* src) {
    asm volatile("cp.async.cg.shared.global [%0], [%1], 16;" :: "r"(dst), "l"(src));
}
__device__ __forceinline__ void ldm4(uint32_t* d, uint32_t addr) {
    asm volatile("ldmatrix.sync.aligned.m8n8.x4.shared.b16 {%0,%1,%2,%3}, [%4];"
        : "=r"(d[0]), "=r"(d[1]), "=r"(d[2]), "=r"(d[3]) : "r"(addr));
}
__device__ __forceinline__ void mma16816(float* c, const uint32_t* a, const uint32_t* b) {
    asm volatile("mma.sync.aligned.m16n8k16.row.col.f32.bf16.bf16.f32 "
        "{%0,%1,%2,%3}, {%4,%5,%6,%7}, {%8,%9}, {%0,%1,%2,%3};"
        : "+f"(c[0]), "+f"(c[1]), "+f"(c[2]), "+f"(c[3])
        : "r"(a[0]), "r"(a[1]), "r"(a[2]), "r"(a[3]), "r"(b[0]), "r"(b[1]));
}
__device__ __forceinline__ void split_w4(__nv_bfloat16* dst, int K, float4 v) {
    float vv[4] = {v.x, v.y, v.z, v.w};
    __nv_bfloat16 hi[4], lo[4];
#pragma unroll
    for (int j = 0; j < 4; j++) {
        hi[j] = __float2bfloat16(vv[j]);
        lo[j] = __float2bfloat16(vv[j] - __bfloat162float(hi[j]));
    }
    *(uint64_t*)(dst)     = *(const uint64_t*)hi;
    *(uint64_t*)(dst + K) = *(const uint64_t*)lo;
}

// ---------------- prep ----------------
#define B0 524288LL
#define B1 (B0 + 262144LL)
#define B2 (B1 + 262144LL)
#define B3 (B2 + 1671168LL)
#define B4 (B3 + 655360LL)
#define B5 (B4 + 262144LL)
#define B6 (B5 + 5242880LL)

__global__ void prep_all(const int* __restrict__ labels, const float* __restrict__ embed,
                         const float* __restrict__ W_frame, const float* __restrict__ W_ih,
                         const float* __restrict__ W_out, const float* __restrict__ W_hh,
                         const float* __restrict__ feats,
                         __nv_bfloat16* __restrict__ Wf2,
                         __nv_bfloat16* __restrict__ Wih2e, __nv_bfloat16* __restrict__ Wih2d,
                         __nv_bfloat16* __restrict__ Wo2, __nv_bfloat16* __restrict__ dece2,
                         __nv_bfloat16* __restrict__ Whh2, __nv_bfloat16* __restrict__ feats2)
{
    const long long stride = (long long)gridDim.x * blockDim.x;
    for (long long i = (long long)blockIdx.x * blockDim.x + threadIdx.x; i < B6; i += stride) {
        if (i < B0) {
            int r = (int)(i >> 10), c4 = ((int)i & 1023) << 2;
            float4 v = *(const float4*)(W_frame + (size_t)r * FDIM + c4);
            split_w4(Wf2 + (size_t)r * (2 * FDIM) + c4, FDIM, v);
        } else if (i < B2) {
            long long j = i - B0;
            int dec = (j >= 262144LL);
            if (dec) j -= 262144LL;
            int r = (int)(j >> 7), c4 = ((int)j & 127) << 2;
            float4 v = *(const float4*)(W_ih + (size_t)r * 1024 + (dec ? 512 : 0) + c4);
            split_w4((dec ? Wih2d : Wih2e) + (size_t)r * 1024 + c4, 512, v);
        } else if (i < B3) {
            long long j = i - B2;
            int r = (int)(j >> 7), c4 = ((int)j & 127) << 2;
            float4 v = make_float4(0.f, 0.f, 0.f, 0.f);
            if (r < VDIM) v = *(const float4*)(W_out + (size_t)r * HDIM + c4);
            split_w4(Wo2 + (size_t)r * 1024 + c4, 512, v);
        } else if (i < B4) {
            long long j = i - B3;
            int r = (int)(j >> 7), c4 = ((int)j & 127) << 2;   // r = t*64+b
            int t = r >> 6, b = r & 63;
            int id = (t == 0) ? START_ID : labels[b * TSTEPS + (t - 1)];
            float4 v = *(const float4*)(embed + (size_t)id * EDIM + c4);
            split_w4(dece2 + (size_t)r * 1024 + c4, 512, v);
        } else if (i < B5) {
            long long j = i - B4;
            int r = (int)(j >> 7), c4 = ((int)j & 127) << 2;
            float4 v = *(const float4*)(W_hh + (size_t)r * HDIM + c4);
            split_w4(Whh2 + (size_t)r * 1024 + c4, 512, v);
        } else {
            long long j = i - B5;
            int r = (int)(j >> 10), c4 = ((int)j & 1023) << 2;
            float4 v = *(const float4*)(feats + (size_t)r * FDIM + c4);
            split_w4(feats2 + (size_t)r * (2 * FDIM) + c4, FDIM, v);
        }
    }
}

// ---------------- mma.sync bf16 GEMM, 2-seg exact-split, CTA tile 128x256 ----------------
#define STAGE 49152

__device__ __forceinline__ void ld_chunk(uint32_t sbase,
    const __nv_bfloat16* __restrict__ Ab, const __nv_bfloat16* __restrict__ Bb,
    int lda, int ao, int bo, int tid)
{
    const __nv_bfloat16* ap = Ab + ao;
    const __nv_bfloat16* bp = Bb + bo;
#pragma unroll
    for (int u = 0; u < 4; u++) {
        int idx = u * 256 + tid, r = idx >> 3, q = idx & 7;
        cpasync16(sbase + r * 128 + ((q ^ (r & 7)) << 4), ap + (size_t)r * lda + q * 8);
    }
#pragma unroll
    for (int u = 0; u < 8; u++) {
        int idx = u * 256 + tid, r = idx >> 3, q = idx & 7;
        cpasync16(sbase + 16384 + r * 128 + ((q ^ (r & 7)) << 4), bp + (size_t)r * lda + q * 8);
    }
}

__global__ __launch_bounds__(256, 1) void mma_tc(
    const __nv_bfloat16* __restrict__ A, const __nv_bfloat16* __restrict__ Aalt,
    int MsplitBlk, int rowOffAlt,
    const __nv_bfloat16* __restrict__ B, const __nv_bfloat16* __restrict__ Balt,
    const float* __restrict__ bias1, const float* __restrict__ bias2,
    void* __restrict__ Cv, int K, int Nreal, int ldc, int outMode, int outBf)
{
    extern __shared__ char smc[];
    const uint32_t sbase = s2u(smc);
    const int tid = threadIdx.x, lane = tid & 31, wid = tid >> 5;
    const int wn = wid & 3, wm = wid >> 2;
    const int bx = blockIdx.x;
    const bool alt = (Aalt != nullptr) && (bx >= MsplitBlk);
    const int m0 = (alt ? bx - MsplitBlk : bx) * 128;
    const int n0 = blockIdx.y * 256;
    const int rowOff = alt ? rowOffAlt : 0;
    const int lda = 2 * K;
    const int KC = K >> 6, NC = 3 * KC;
    const __nv_bfloat16* Ab = (alt ? Aalt : A) + (size_t)m0 * lda;
    const __nv_bfloat16* Bb = (alt ? Balt : B) + (size_t)n0 * lda;

    float acc[4][8][4];
#pragma unroll
    for (int a = 0; a < 4; a++)
#pragma unroll
        for (int b = 0; b < 8; b++)
#pragma unroll
            for (int d = 0; d < 4; d++) acc[a][b][d] = 0.f;

    ld_chunk(sbase, Ab, Bb, lda, 0, 0, tid);
    asm volatile("cp.async.commit_group;" ::: "memory");

    int segN = 0, kcN = 0;
    for (int c = 0; c < NC; c++) {
        asm volatile("cp.async.wait_group 0;" ::: "memory");
        __syncthreads();

        if (c + 1 < NC) {
            if (++kcN == KC) { kcN = 0; segN++; }
            int ao = ((segN == 2) ? K : 0) + (kcN << 6);
            int bo = ((segN == 1) ? K : 0) + (kcN << 6);
            ld_chunk(sbase + ((c + 1) & 1) * STAGE, Ab, Bb, lda, ao, bo, tid);
            asm volatile("cp.async.commit_group;" ::: "memory");
        }

        const uint32_t sa = sbase + (c & 1) * STAGE;
        const uint32_t sb = sa + 16384;
#pragma unroll
        for (int ks = 0; ks < 4; ks++) {
            uint32_t af[4][4];
#pragma unroll
            for (int mt = 0; mt < 4; mt++) {
                int r = wm * 64 + mt * 16 + (lane & 15);
                int q = 2 * ks + (lane >> 4);
                ldm4(af[mt], sa + r * 128 + ((q ^ (r & 7)) << 4));
            }
            uint32_t bf[4][4];
#pragma unroll
            for (int bp2 = 0; bp2 < 4; bp2++) {
                int r = wn * 64 + (bp2 * 2 + (lane >> 4)) * 8 + (lane & 7);
                int q = 2 * ks + ((lane >> 3) & 1);
                ldm4(bf[bp2], sb + r * 128 + ((q ^ (r & 7)) << 4));
            }
#pragma unroll
            for (int mt = 0; mt < 4; mt++)
#pragma unroll
                for (int nt = 0; nt < 8; nt++)
                    mma16816(acc[mt][nt], af[mt], &bf[nt >> 1][(nt & 1) * 2]);
        }
    }

    const int mb = m0 + wm * 64, nb = n0 + wn * 64;
#pragma unroll
    for (int mt = 0; mt < 4; mt++)
#pragma unroll
        for (int half = 0; half < 2; half++) {
            int r = mb + mt * 16 + (lane >> 2) + half * 8;
            int rr;
            if (outMode == 1)      rr = (r & 63) * 80 + (r >> 6);   // t-major -> b*80+t
            else if (outMode == 2) rr = (r % 80) * 64 + (r / 80);   // b-major -> t*64+b
            else                   rr = r + rowOff;
#pragma unroll
            for (int nt = 0; nt < 8; nt++) {
                int cb = nb + nt * 8 + (lane & 3) * 2;
                if (cb < Nreal) {
                    float2 bv = *(const float2*)(bias1 + cb);
                    if (bias2) {
                        float2 b2 = *(const float2*)(bias2 + cb);
                        bv.x += b2.x; bv.y += b2.y;
                    }
                    float vx = acc[mt][nt][half * 2 + 0] + bv.x;
                    float vy = acc[mt][nt][half * 2 + 1] + bv.y;
                    if (outBf) {
                        __nv_bfloat16* op = (__nv_bfloat16*)Cv + (size_t)rr * ldc;
                        __nv_bfloat16 h0 = __float2bfloat16(vx), h1 = __float2bfloat16(vy);
                        __nv_bfloat16 l0 = __float2bfloat16(vx - __bfloat162float(h0));
                        __nv_bfloat16 l1 = __float2bfloat16(vy - __bfloat162float(h1));
                        *(__nv_bfloat162*)(op + cb)         = __halves2bfloat162(h0, h1);
                        *(__nv_bfloat162*)(op + Nreal + cb) = __halves2bfloat162(l0, l1);
                    } else {
                        float* op = (float*)Cv + (size_t)rr * ldc;
                        *(float2*)(op + cb) = make_float2(vx, vy);
                    }
                }
            }
        }
}

// ---------------- persistent LSTM on tensor cores ----------------
#define LCTAS 64
#define SM_B_OFF 131072
#define SM_G_OFF 196608
#define SM_H_OFF (196608 + 64 * 33 * 4)
#define LSMEM    (SM_H_OFF + 2048)

__device__ __forceinline__ float sigf(float x) {
    return __fdividef(1.f, 1.f + __expf(-x));
}
__device__ __forceinline__ float tanhfast(float x) {
    float e = __expf(-2.f * fabsf(x));
    float t = __fdividef(1.f - e, 1.f + e);
    return copysignf(t, x);
}

// two-level tree barrier; gen is caller-cached (incremented by caller each use)
__device__ __forceinline__ void gsync_tree(unsigned gen)
{
    __syncthreads();
    if (threadIdx.x == 0) {
        const int grp = blockIdx.x >> 3;
        unsigned old;
        asm volatile("atom.acq_rel.gpu.global.add.u32 %0, [%1], 1;"
                     : "=r"(old) : "l"(&g_grp[grp * 64]) : "memory");
        if (old == 7) {
            unsigned o2;
            asm volatile("atom.acq_rel.gpu.global.add.u32 %0, [%1], 1;"
                         : "=r"(o2) : "l"(&g_cnt_top) : "memory");
            if (o2 == 7) {
#pragma unroll
                for (int i = 0; i < 8; i++)
                    asm volatile("st.relaxed.gpu.global.u32 [%0], %1;"
                                 :: "l"(&g_grp[i * 64]), "r"(0u) : "memory");
                asm volatile("st.relaxed.gpu.global.u32 [%0], %1;"
                             :: "l"(&g_cnt_top), "r"(0u) : "memory");
                asm volatile("st.release.gpu.global.u32 [%0], %1;"
                             :: "l"(&g_bar_gen), "r"(gen + 1u) : "memory");
            }
        }
        unsigned g;
        do {
            asm volatile("ld.acquire.gpu.global.u32 %0, [%1];" : "=r"(g) : "l"(&g_bar_gen) : "memory");
        } while ((int)(g - (gen + 1u)) < 0);
    }
    __syncthreads();
}

__global__ __launch_bounds__(256, 1) void lstm_tc(
    const __nv_bfloat16* __restrict__ Whh2, const float* __restrict__ xg,
    __nv_bfloat16* __restrict__ hh2, __nv_bfloat16* __restrict__ hb)
{
    extern __shared__ char sml[];
    const uint32_t sb = s2u(sml);
    float* gs = (float*)(sml + SM_G_OFF);
    __nv_bfloat16* hex = (__nv_bfloat16*)(sml + SM_H_OFF);
    const int tid = threadIdx.x, lane = tid & 31, wid = tid >> 5;
    const int wm = wid & 3, wn = wid >> 2;     // 4 m-tiles(16) x 2 n-tiles(16)
    const int ct = blockIdx.x;

    // cached barrier generation (safe: gen cannot advance before this CTA's first arrival)
    unsigned gen;
    asm volatile("ld.relaxed.gpu.global.u32 %0, [%1];" : "=r"(gen) : "l"(&g_bar_gen) : "memory");

    // W tile: smem row n = h*4+g <- global row g*512 + ct*8 + h
#pragma unroll
    for (int u = 0; u < 16; u++) {
        int idx = u * 256 + tid;
        int n = idx >> 7, rem = idx & 127, pl = rem >> 3, q = rem & 7;
        int h = n >> 2, g = n & 3;
        cpasync16(sb + SM_B_OFF + pl * 4096 + n * 128 + ((q ^ (n & 7)) << 4),
                  Whh2 + (size_t)(g * 512 + ct * 8 + h) * 1024 + pl * 64 + q * 8);
    }
    asm volatile("cp.async.commit_group;" ::: "memory");
    *(uint64_t*)((char*)hb + ct * 2048 + tid * 8) = 0ull;   // zero hbuf[0]
    asm volatile("cp.async.wait_group 0;" ::: "memory");

    float c0 = 0.f, c1 = 0.f;
    gsync_tree(gen); gen++;

    int cur = 0;
    for (int s = 0; s < NSTEPS; s++) {
        const __nv_bfloat16* hbc = hb + cur * (BATCH * 1024);
        // group 1: hi planes (0-7) — needed by segs 0 and 1
#pragma unroll
        for (int u = 0; u < 16; u++) {
            int idx = u * 256 + tid;
            int pl = idx >> 9, r = (idx >> 3) & 63, q = idx & 7;
            cpasync16(sb + pl * 8192 + r * 128 + ((q ^ (r & 7)) << 4),
                      hbc + (size_t)r * 1024 + pl * 64 + q * 8);
        }
        asm volatile("cp.async.commit_group;" ::: "memory");
        // group 2: lo planes (8-15) — needed by seg 2 only
#pragma unroll
        for (int u = 16; u < 32; u++) {
            int idx = u * 256 + tid;
            int pl = idx >> 9, r = (idx >> 3) & 63, q = idx & 7;
            cpasync16(sb + pl * 8192 + r * 128 + ((q ^ (r & 7)) << 4),
                      hbc + (size_t)r * 1024 + pl * 64 + q * 8);
        }
        asm volatile("cp.async.commit_group;" ::: "memory");

        float xr[2][4];
#pragma unroll
        for (int p = 0; p < 2; p++) {
            int idx = tid + p * 256;
            int b = idx & 63, hl = idx >> 6;
            const float* xp = xg + (size_t)(s * 64 + b) * GDIM + ct * 8 + hl;
#pragma unroll
            for (int g = 0; g < 4; g++) xr[p][g] = __ldg(xp + g * 512);
        }

        float acc[2][4];
#pragma unroll
        for (int nt = 0; nt < 2; nt++)
#pragma unroll
            for (int d = 0; d < 4; d++) acc[nt][d] = 0.f;

        // wait hi planes only, run segs 0-1 while lo planes stream in
        asm volatile("cp.async.wait_group 1;" ::: "memory");
        __syncthreads();

#pragma unroll
        for (int seg = 0; seg < 2; seg++) {
            const int pb = (seg == 1) ? 8 : 0;
#pragma unroll
            for (int kc = 0; kc < 8; kc++) {
                const uint32_t abase = sb + kc * 8192;
                const uint32_t bbase = sb + SM_B_OFF + (pb + kc) * 4096;
#pragma unroll
                for (int ks = 0; ks < 4; ks++) {
                    uint32_t af[4], bf[4];
                    {
                        int r = wm * 16 + (lane & 15);
                        int q = 2 * ks + (lane >> 4);
                        ldm4(af, abase + r * 128 + ((q ^ (r & 7)) << 4));
                    }
                    {
                        int r = wn * 16 + (lane >> 4) * 8 + (lane & 7);
                        int q = 2 * ks + ((lane >> 3) & 1);
                        ldm4(bf, bbase + r * 128 + ((q ^ (r & 7)) << 4));
                    }
                    mma16816(acc[0], af, &bf[0]);
                    mma16816(acc[1], af, &bf[2]);
                }
            }
        }

        asm volatile("cp.async.wait_group 0;" ::: "memory");
        __syncthreads();

        // seg 2: lo(h) x hi(W)
#pragma unroll
        for (int kc = 0; kc < 8; kc++) {
            const uint32_t abase = sb + (8 + kc) * 8192;
            const uint32_t bbase = sb + SM_B_OFF + kc * 4096;
#pragma unroll
            for (int ks = 0; ks < 4; ks++) {
                uint32_t af[4], bf[4];
                {
                    int r = wm * 16 + (lane & 15);
                    int q = 2 * ks + (lane >> 4);
                    ldm4(af, abase + r * 128 + ((q ^ (r & 7)) << 4));
                }
                {
                    int r = wn * 16 + (lane >> 4) * 8 + (lane & 7);
                    int q = 2 * ks + ((lane >> 3) & 1);
                    ldm4(bf, bbase + r * 128 + ((q ^ (r & 7)) << 4));
                }
                mma16816(acc[0], af, &bf[0]);
                mma16816(acc[1], af, &bf[2]);
            }
        }

#pragma unroll
        for (int nt = 0; nt < 2; nt++) {
            int col = wn * 16 + nt * 8 + (lane & 3) * 2;
            int row = wm * 16 + (lane >> 2);
            gs[row * 33 + col]           = acc[nt][0];
            gs[row * 33 + col + 1]       = acc[nt][1];
            gs[(row + 8) * 33 + col]     = acc[nt][2];
            gs[(row + 8) * 33 + col + 1] = acc[nt][3];
        }
        __syncthreads();

#pragma unroll
        for (int p = 0; p < 2; p++) {
            int idx = tid + p * 256;
            int b = idx & 63, hl = idx >> 6;
            float gi = gs[b * 33 + hl * 4 + 0] + xr[p][0];
            float gf = gs[b * 33 + hl * 4 + 1] + xr[p][1];
            float gg = gs[b * 33 + hl * 4 + 2] + xr[p][2];
            float go = gs[b * 33 + hl * 4 + 3] + xr[p][3];
            float iv = sigf(gi), fv = sigf(gf), gv = tanhfast(gg), ov = sigf(go);
            float cc = (p ? c1 : c0);
            cc = fv * cc + iv * gv;
            if (p) c1 = cc; else c0 = cc;
            float hv = ov * tanhfast(cc);
            __nv_bfloat16 hbv = __float2bfloat16(hv);
            __nv_bfloat16 lbv = __float2bfloat16(hv - __bfloat162float(hbv));
            hex[b * 8 + hl]       = hbv;
            hex[512 + b * 8 + hl] = lbv;
        }
        __syncthreads();

        // coalesced 16B global stores
        if (tid < 128) {
            int half = tid >> 6, b = tid & 63;
            uint4 v = *(const uint4*)(hex + half * 512 + b * 8);
            __nv_bfloat16* hbn = hb + (cur ^ 1) * (BATCH * 1024);
            *(uint4*)(hbn + (size_t)b * 1024 + half * 512 + ct * 8) = v;
            if (s >= TSTEPS) {
                int t = s - TSTEPS;
                *(uint4*)(hh2 + (size_t)(t * 64 + b) * 1024 + half * 512 + ct * 8) = v;
            }
        }

        gsync_tree(gen); gen++;
        cur ^= 1;
    }
}

// ---------------- launch ----------------
extern "C" void kernel_launch(void* const* d_in, const int* in_sizes, int n_in,
                              void* d_out, int out_size)
{
    const float* feats   = (const float*)d_in[0];
    const int*   labels  = (const int*)  d_in[1];
    const float* W_frame = (const float*)d_in[2];
    const float* b_frame = (const float*)d_in[3];
    const float* embed   = (const float*)d_in[4];
    const float* W_ih    = (const float*)d_in[5];
    const float* W_hh    = (const float*)d_in[6];
    const float* b_ih    = (const float*)d_in[7];
    const float* b_hh    = (const float*)d_in[8];
    const float* W_out   = (const float*)d_in[9];
    const float* b_out   = (const float*)d_in[10];
    float* out = (float*)d_out;

    float* p_xgate;
    __nv_bfloat16 *p_feats2, *p_Wf2, *p_emb2, *p_Wih2e, *p_Wih2d, *p_dece2, *p_Whh2, *p_hh2, *p_Wo2, *p_hb;
    cudaGetSymbolAddress((void**)&p_xgate,  g_xgate);
    cudaGetSymbolAddress((void**)&p_feats2, g_feats2);
    cudaGetSymbolAddress((void**)&p_Wf2,    g_Wf2);
    cudaGetSymbolAddress((void**)&p_emb2,   g_emb2);
    cudaGetSymbolAddress((void**)&p_Wih2e,  g_Wih2e);
    cudaGetSymbolAddress((void**)&p_Wih2d,  g_Wih2d);
    cudaGetSymbolAddress((void**)&p_dece2,  g_dece2);
    cudaGetSymbolAddress((void**)&p_Whh2,   g_Whh2);
    cudaGetSymbolAddress((void**)&p_hh2,    g_hh2);
    cudaGetSymbolAddress((void**)&p_Wo2,    g_Wo2);
    cudaGetSymbolAddress((void**)&p_hb,     g_hbufb);

    cudaFuncSetAttribute(lstm_tc, cudaFuncAttributeMaxDynamicSharedMemorySize, LSMEM);
    const int smem_tc = 2 * STAGE;
    cudaFuncSetAttribute(mma_tc, cudaFuncAttributeMaxDynamicSharedMemorySize, smem_tc);

    // [0] prep
    prep_all<<<1480, 256>>>(labels, embed, W_frame, W_ih, W_out, W_hh, feats,
                            p_Wf2, p_Wih2e, p_Wih2d, p_Wo2, p_dece2, p_Whh2, p_feats2);
    // [1] frame embedding -> g_emb2 (bf16 dual, t-major rows), K=4096
    {
        dim3 grid(MROWS / 128, EDIM / 256);
        mma_tc<<<grid, 256, smem_tc>>>(p_feats2, nullptr, 1 << 30, 0, p_Wf2, nullptr,
                                       b_frame, nullptr, p_emb2, FDIM, EDIM, 2 * EDIM, 2, 1);
    }
    // [2] both x-gate GEMMs fused (enc m-blocks 0-39, dec 40-79), K=512
    {
        dim3 grid(2 * (MROWS / 128), GDIM / 256);
        mma_tc<<<grid, 256, smem_tc>>>(p_emb2, p_dece2, MROWS / 128, MROWS,
                                       p_Wih2e, p_Wih2d, b_ih, b_hh,
                                       p_xgate, EDIM, GDIM, GDIM, 0, 0);
    }
    // [3] recurrence  <-- profiled launch
    lstm_tc<<<LCTAS, 256, LSMEM>>>(p_Whh2, p_xgate, p_hh2, p_hb);
    // [4] logits, K=512, t-major -> b-major remap
    {
        dim3 grid(MROWS / 128, VPAD / 256);
        mma_tc<<<grid, 256, smem_tc>>>(p_hh2, nullptr, 1 << 30, 0, p_Wo2, nullptr,
                                       b_out, nullptr, out, HDIM, VDIM, VDIM, 1, 0);
    }
}

// round 17
// speedup vs baseline: 1.2156x; 1.0030x over previous
#include <cuda_runtime.h>
#include <cuda_bf16.h>
#include <math.h>
#include <stdint.h>

#define TSTEPS 80
#define BATCH  64
#define FDIM   4096
#define EDIM   512
#define HDIM   512
#define VDIM   13000
#define VPAD   13056
#define GDIM   2048
#define NSTEPS 160
#define MROWS  5120
#define START_ID 1

// ---------------- scratch ----------------
__device__ __align__(16) __nv_bfloat16 g_feats2[(size_t)MROWS * 2 * FDIM];   // [hi|lo]
__device__ __align__(16) __nv_bfloat16 g_Wf2   [(size_t)EDIM  * 2 * FDIM];
__device__ __align__(16) __nv_bfloat16 g_emb2  [(size_t)MROWS * 2 * EDIM];   // t-major rows
__device__ __align__(16) __nv_bfloat16 g_Wih2e [(size_t)GDIM  * 2 * EDIM];
__device__ __align__(16) __nv_bfloat16 g_Wih2d [(size_t)GDIM  * 2 * EDIM];
__device__ __align__(16) __nv_bfloat16 g_dece2 [(size_t)MROWS * 2 * EDIM];   // t-major rows
__device__ __align__(16) __nv_bfloat16 g_Whh2  [(size_t)GDIM  * 2 * HDIM];   // [hi|lo]
__device__ __align__(16) float         g_xgate [(size_t)NSTEPS * BATCH * GDIM]; // [s*64+b][2048]
__device__ __align__(16) __nv_bfloat16 g_hh2   [(size_t)MROWS * 2 * HDIM];   // t-major rows
__device__ __align__(16) __nv_bfloat16 g_Wo2   [(size_t)VPAD  * 2 * HDIM];
__device__ __align__(16) __nv_bfloat16 g_hbufb [2][BATCH * 1024];            // h ping-pong bf16 [hi|lo]
// barrier state: tree (8 groups x 8), each counter on a private 256B line
__device__ __align__(256) unsigned g_grp[8 * 64];
__device__ __align__(256) unsigned g_cnt_top;
__device__ __align__(256) unsigned g_bar_gen;

// ---------------- generic-PTX helpers ----------------
__device__ __forceinline__ uint32_t s2u(const void* p) {
    uint32_t a;
    asm("{ .reg .u64 t; cvta.to.shared.u64 t, %1; cvt.u32.u64 %0, t; }" : "=r"(a) : "l"(p));
    return a;
}
__device__ __forceinline__ void cpasync16(uint32_t dst, const void* src) {
    asm volatile("cp.async.cg.shared.global [%0], [%1], 16;" :: "r"(dst), "l"(src));
}
__device__ __forceinline__ void ldm4(uint32_t* d, uint32_t addr) {
    asm volatile("ldmatrix.sync.aligned.m8n8.x4.shared.b16 {%0,%1,%2,%3}, [%4];"
        : "=r"(d[0]), "=r"(d[1]), "=r"(d[2]), "=r"(d[3]) : "r"(addr));
}
__device__ __forceinline__ void mma16816(float* c, const uint32_t* a, const uint32_t* b) {
    asm volatile("mma.sync.aligned.m16n8k16.row.col.f32.bf16.bf16.f32 "
        "{%0,%1,%2,%3}, {%4,%5,%6,%7}, {%8,%9}, {%0,%1,%2,%3};"
        : "+f"(c[0]), "+f"(c[1]), "+f"(c[2]), "+f"(c[3])
        : "r"(a[0]), "r"(a[1]), "r"(a[2]), "r"(a[3]), "r"(b[0]), "r"(b[1]));
}
__device__ __forceinline__ void split_w4(__nv_bfloat16* dst, int K, float4 v) {
    float vv[4] = {v.x, v.y, v.z, v.w};
    __nv_bfloat16 hi[4], lo[4];
#pragma unroll
    for (int j = 0; j < 4; j++) {
        hi[j] = __float2bfloat16(vv[j]);
        lo[j] = __float2bfloat16(vv[j] - __bfloat162float(hi[j]));
    }
    *(uint64_t*)(dst)     = *(const uint64_t*)hi;
    *(uint64_t*)(dst + K) = *(const uint64_t*)lo;
}

// ---------------- prep ----------------
#define B0 524288LL
#define B1 (B0 + 262144LL)
#define B2 (B1 + 262144LL)
#define B3 (B2 + 1671168LL)
#define B4 (B3 + 655360LL)
#define B5 (B4 + 262144LL)
#define B6 (B5 + 5242880LL)

__global__ void prep_all(const int* __restrict__ labels, const float* __restrict__ embed,
                         const float* __restrict__ W_frame, const float* __restrict__ W_ih,
                         const float* __restrict__ W_out, const float* __restrict__ W_hh,
                         const float* __restrict__ feats,
                         __nv_bfloat16* __restrict__ Wf2,
                         __nv_bfloat16* __restrict__ Wih2e, __nv_bfloat16* __restrict__ Wih2d,
                         __nv_bfloat16* __restrict__ Wo2, __nv_bfloat16* __restrict__ dece2,
                         __nv_bfloat16* __restrict__ Whh2, __nv_bfloat16* __restrict__ feats2)
{
    const long long stride = (long long)gridDim.x * blockDim.x;
    for (long long i = (long long)blockIdx.x * blockDim.x + threadIdx.x; i < B6; i += stride) {
        if (i < B0) {
            int r = (int)(i >> 10), c4 = ((int)i & 1023) << 2;
            float4 v = *(const float4*)(W_frame + (size_t)r * FDIM + c4);
            split_w4(Wf2 + (size_t)r * (2 * FDIM) + c4, FDIM, v);
        } else if (i < B2) {
            long long j = i - B0;
            int dec = (j >= 262144LL);
            if (dec) j -= 262144LL;
            int r = (int)(j >> 7), c4 = ((int)j & 127) << 2;
            float4 v = *(const float4*)(W_ih + (size_t)r * 1024 + (dec ? 512 : 0) + c4);
            split_w4((dec ? Wih2d : Wih2e) + (size_t)r * 1024 + c4, 512, v);
        } else if (i < B3) {
            long long j = i - B2;
            int r = (int)(j >> 7), c4 = ((int)j & 127) << 2;
            float4 v = make_float4(0.f, 0.f, 0.f, 0.f);
            if (r < VDIM) v = *(const float4*)(W_out + (size_t)r * HDIM + c4);
            split_w4(Wo2 + (size_t)r * 1024 + c4, 512, v);
        } else if (i < B4) {
            long long j = i - B3;
            int r = (int)(j >> 7), c4 = ((int)j & 127) << 2;   // r = t*64+b
            int t = r >> 6, b = r & 63;
            int id = (t == 0) ? START_ID : labels[b * TSTEPS + (t - 1)];
            float4 v = *(const float4*)(embed + (size_t)id * EDIM + c4);
            split_w4(dece2 + (size_t)r * 1024 + c4, 512, v);
        } else if (i < B5) {
            long long j = i - B4;
            int r = (int)(j >> 7), c4 = ((int)j & 127) << 2;
            float4 v = *(const float4*)(W_hh + (size_t)r * HDIM + c4);
            split_w4(Whh2 + (size_t)r * 1024 + c4, 512, v);
        } else {
            long long j = i - B5;
            int r = (int)(j >> 10), c4 = ((int)j & 1023) << 2;
            float4 v = *(const float4*)(feats + (size_t)r * FDIM + c4);
            split_w4(feats2 + (size_t)r * (2 * FDIM) + c4, FDIM, v);
        }
    }
}

// ---------------- mma.sync bf16 GEMM, load-once-all-halves chunks, CTA tile 128x256 ----------------
// Stage layout: A-hi 16KB @0 | A-lo @16384 | B-hi 32KB @32768 | B-lo @65536.  Stage = 96KB.
#define STG 98304

__device__ __forceinline__ void ld_chunk2(uint32_t sbase,
    const __nv_bfloat16* __restrict__ Ab, const __nv_bfloat16* __restrict__ Bb,
    int lda, int K, int co, int tid)
{
#pragma unroll
    for (int u = 0; u < 4; u++) {              // A-hi: 128 rows x 64 cols
        int idx = u * 256 + tid, r = idx >> 3, q = idx & 7;
        cpasync16(sbase + r * 128 + ((q ^ (r & 7)) << 4), Ab + (size_t)r * lda + co + q * 8);
    }
#pragma unroll
    for (int u = 0; u < 4; u++) {              // A-lo
        int idx = u * 256 + tid, r = idx >> 3, q = idx & 7;
        cpasync16(sbase + 16384 + r * 128 + ((q ^ (r & 7)) << 4), Ab + (size_t)r * lda + K + co + q * 8);
    }
#pragma unroll
    for (int u = 0; u < 8; u++) {              // B-hi: 256 rows x 64 cols
        int idx = u * 256 + tid, r = idx >> 3, q = idx & 7;
        cpasync16(sbase + 32768 + r * 128 + ((q ^ (r & 7)) << 4), Bb + (size_t)r * lda + co + q * 8);
    }
#pragma unroll
    for (int u = 0; u < 8; u++) {              // B-lo
        int idx = u * 256 + tid, r = idx >> 3, q = idx & 7;
        cpasync16(sbase + 65536 + r * 128 + ((q ^ (r & 7)) << 4), Bb + (size_t)r * lda + K + co + q * 8);
    }
}

__global__ __launch_bounds__(256, 1) void mma_tc(
    const __nv_bfloat16* __restrict__ A, const __nv_bfloat16* __restrict__ Aalt,
    int MsplitBlk, int rowOffAlt,
    const __nv_bfloat16* __restrict__ B, const __nv_bfloat16* __restrict__ Balt,
    const float* __restrict__ bias1, const float* __restrict__ bias2,
    void* __restrict__ Cv, int K, int Nreal, int ldc, int outMode, int outBf)
{
    extern __shared__ char smc[];
    const uint32_t sbase = s2u(smc);
    const int tid = threadIdx.x, lane = tid & 31, wid = tid >> 5;
    const int wn = wid & 3, wm = wid >> 2;
    const int bx = blockIdx.x;
    const bool alt = (Aalt != nullptr) && (bx >= MsplitBlk);
    const int m0 = (alt ? bx - MsplitBlk : bx) * 128;
    const int n0 = blockIdx.y * 256;
    const int rowOff = alt ? rowOffAlt : 0;
    const int lda = 2 * K;
    const int KC = K >> 6;
    const __nv_bfloat16* Ab = (alt ? Aalt : A) + (size_t)m0 * lda;
    const __nv_bfloat16* Bb = (alt ? Balt : B) + (size_t)n0 * lda;

    float acc[4][8][4];
#pragma unroll
    for (int a = 0; a < 4; a++)
#pragma unroll
        for (int b = 0; b < 8; b++)
#pragma unroll
            for (int d = 0; d < 4; d++) acc[a][b][d] = 0.f;

    ld_chunk2(sbase, Ab, Bb, lda, K, 0, tid);
    asm volatile("cp.async.commit_group;" ::: "memory");

    for (int c = 0; c < KC; c++) {
        asm volatile("cp.async.wait_group 0;" ::: "memory");
        __syncthreads();

        if (c + 1 < KC) {
            ld_chunk2(sbase + ((c + 1) & 1) * STG, Ab, Bb, lda, K, (c + 1) << 6, tid);
            asm volatile("cp.async.commit_group;" ::: "memory");
        }

        const uint32_t st = sbase + (c & 1) * STG;
        // 3 exact-split segments on resident data:
        // seg0: A-hi x B-hi, seg1: A-hi x B-lo, seg2: A-lo x B-hi
#pragma unroll
        for (int seg = 0; seg < 3; seg++) {
            const uint32_t sa = st + ((seg == 2) ? 16384 : 0);
            const uint32_t sb = st + 32768 + ((seg == 1) ? 32768 : 0);
#pragma unroll
            for (int ks = 0; ks < 4; ks++) {
                uint32_t af[4][4];
#pragma unroll
                for (int mt = 0; mt < 4; mt++) {
                    int r = wm * 64 + mt * 16 + (lane & 15);
                    int q = 2 * ks + (lane >> 4);
                    ldm4(af[mt], sa + r * 128 + ((q ^ (r & 7)) << 4));
                }
                uint32_t bf[4][4];
#pragma unroll
                for (int bp2 = 0; bp2 < 4; bp2++) {
                    int r = wn * 64 + (bp2 * 2 + (lane >> 4)) * 8 + (lane & 7);
                    int q = 2 * ks + ((lane >> 3) & 1);
                    ldm4(bf[bp2], sb + r * 128 + ((q ^ (r & 7)) << 4));
                }
#pragma unroll
                for (int mt = 0; mt < 4; mt++)
#pragma unroll
                    for (int nt = 0; nt < 8; nt++)
                        mma16816(acc[mt][nt], af[mt], &bf[nt >> 1][(nt & 1) * 2]);
            }
        }
    }

    const int mb = m0 + wm * 64, nb = n0 + wn * 64;
#pragma unroll
    for (int mt = 0; mt < 4; mt++)
#pragma unroll
        for (int half = 0; half < 2; half++) {
            int r = mb + mt * 16 + (lane >> 2) + half * 8;
            int rr;
            if (outMode == 1)      rr = (r & 63) * 80 + (r >> 6);   // t-major -> b*80+t
            else if (outMode == 2) rr = (r % 80) * 64 + (r / 80);   // b-major -> t*64+b
            else                   rr = r + rowOff;
#pragma unroll
            for (int nt = 0; nt < 8; nt++) {
                int cb = nb + nt * 8 + (lane & 3) * 2;
                if (cb < Nreal) {
                    float2 bv = *(const float2*)(bias1 + cb);
                    if (bias2) {
                        float2 b2 = *(const float2*)(bias2 + cb);
                        bv.x += b2.x; bv.y += b2.y;
                    }
                    float vx = acc[mt][nt][half * 2 + 0] + bv.x;
                    float vy = acc[mt][nt][half * 2 + 1] + bv.y;
                    if (outBf) {
                        __nv_bfloat16* op = (__nv_bfloat16*)Cv + (size_t)rr * ldc;
                        __nv_bfloat16 h0 = __float2bfloat16(vx), h1 = __float2bfloat16(vy);
                        __nv_bfloat16 l0 = __float2bfloat16(vx - __bfloat162float(h0));
                        __nv_bfloat16 l1 = __float2bfloat16(vy - __bfloat162float(h1));
                        *(__nv_bfloat162*)(op + cb)         = __halves2bfloat162(h0, h1);
                        *(__nv_bfloat162*)(op + Nreal + cb) = __halves2bfloat162(l0, l1);
                    } else {
                        float* op = (float*)Cv + (size_t)rr * ldc;
                        *(float2*)(op + cb) = make_float2(vx, vy);
                    }
                }
            }
        }
}

// ---------------- persistent LSTM on tensor cores ----------------
#define LCTAS 64
#define SM_B_OFF 131072
#define SM_G_OFF 196608
#define SM_H_OFF (196608 + 64 * 33 * 4)
#define LSMEM    (SM_H_OFF + 2048)

__device__ __forceinline__ float sigf(float x) {
    return __fdividef(1.f, 1.f + __expf(-x));
}
__device__ __forceinline__ float tanhfast(float x) {
    float e = __expf(-2.f * fabsf(x));
    float t = __fdividef(1.f - e, 1.f + e);
    return copysignf(t, x);
}

// two-level tree barrier; gen is caller-cached
__device__ __forceinline__ void gsync_tree(unsigned gen)
{
    __syncthreads();
    if (threadIdx.x == 0) {
        const int grp = blockIdx.x >> 3;
        unsigned old;
        asm volatile("atom.acq_rel.gpu.global.add.u32 %0, [%1], 1;"
                     : "=r"(old) : "l"(&g_grp[grp * 64]) : "memory");
        if (old == 7) {
            unsigned o2;
            asm volatile("atom.acq_rel.gpu.global.add.u32 %0, [%1], 1;"
                         : "=r"(o2) : "l"(&g_cnt_top) : "memory");
            if (o2 == 7) {
#pragma unroll
                for (int i = 0; i < 8; i++)
                    asm volatile("st.relaxed.gpu.global.u32 [%0], %1;"
                                 :: "l"(&g_grp[i * 64]), "r"(0u) : "memory");
                asm volatile("st.relaxed.gpu.global.u32 [%0], %1;"
                             :: "l"(&g_cnt_top), "r"(0u) : "memory");
                asm volatile("st.release.gpu.global.u32 [%0], %1;"
                             :: "l"(&g_bar_gen), "r"(gen + 1u) : "memory");
            }
        }
        unsigned g;
        do {
            asm volatile("ld.acquire.gpu.global.u32 %0, [%1];" : "=r"(g) : "l"(&g_bar_gen) : "memory");
        } while ((int)(g - (gen + 1u)) < 0);
    }
    __syncthreads();
}

__global__ __launch_bounds__(256, 1) void lstm_tc(
    const __nv_bfloat16* __restrict__ Whh2, const float* __restrict__ xg,
    __nv_bfloat16* __restrict__ hh2, __nv_bfloat16* __restrict__ hb)
{
    extern __shared__ char sml[];
    const uint32_t sb = s2u(sml);
    float* gs = (float*)(sml + SM_G_OFF);
    __nv_bfloat16* hex = (__nv_bfloat16*)(sml + SM_H_OFF);
    const int tid = threadIdx.x, lane = tid & 31, wid = tid >> 5;
    const int wm = wid & 3, wn = wid >> 2;     // 4 m-tiles(16) x 2 n-tiles(16)
    const int ct = blockIdx.x;

    unsigned gen;
    asm volatile("ld.relaxed.gpu.global.u32 %0, [%1];" : "=r"(gen) : "l"(&g_bar_gen) : "memory");

    // W tile: smem row n = h*4+g <- global row g*512 + ct*8 + h
#pragma unroll
    for (int u = 0; u < 16; u++) {
        int idx = u * 256 + tid;
        int n = idx >> 7, rem = idx & 127, pl = rem >> 3, q = rem & 7;
        int h = n >> 2, g = n & 3;
        cpasync16(sb + SM_B_OFF + pl * 4096 + n * 128 + ((q ^ (n & 7)) << 4),
                  Whh2 + (size_t)(g * 512 + ct * 8 + h) * 1024 + pl * 64 + q * 8);
    }
    asm volatile("cp.async.commit_group;" ::: "memory");
    *(uint64_t*)((char*)hb + ct * 2048 + tid * 8) = 0ull;   // zero hbuf[0]
    asm volatile("cp.async.wait_group 0;" ::: "memory");

    float c0 = 0.f, c1 = 0.f;
    gsync_tree(gen); gen++;

    int cur = 0;
    for (int s = 0; s < NSTEPS; s++) {
        const __nv_bfloat16* hbc = hb + cur * (BATCH * 1024);
        // group A: planes 0-3
#pragma unroll
        for (int u = 0; u < 8; u++) {
            int idx = u * 256 + tid;
            int pl = idx >> 9, r = (idx >> 3) & 63, q = idx & 7;
            cpasync16(sb + pl * 8192 + r * 128 + ((q ^ (r & 7)) << 4),
                      hbc + (size_t)r * 1024 + pl * 64 + q * 8);
        }
        asm volatile("cp.async.commit_group;" ::: "memory");
        // group B: planes 4-7
#pragma unroll
        for (int u = 8; u < 16; u++) {
            int idx = u * 256 + tid;
            int pl = idx >> 9, r = (idx >> 3) & 63, q = idx & 7;
            cpasync16(sb + pl * 8192 + r * 128 + ((q ^ (r & 7)) << 4),
                      hbc + (size_t)r * 1024 + pl * 64 + q * 8);
        }
        asm volatile("cp.async.commit_group;" ::: "memory");
        // group C: planes 8-15 (lo half)
#pragma unroll
        for (int u = 16; u < 32; u++) {
            int idx = u * 256 + tid;
            int pl = idx >> 9, r = (idx >> 3) & 63, q = idx & 7;
            cpasync16(sb + pl * 8192 + r * 128 + ((q ^ (r & 7)) << 4),
                      hbc + (size_t)r * 1024 + pl * 64 + q * 8);
        }
        asm volatile("cp.async.commit_group;" ::: "memory");

        float xr[2][4];
#pragma unroll
        for (int p = 0; p < 2; p++) {
            int idx = tid + p * 256;
            int b = idx & 63, hl = idx >> 6;
            const float* xp = xg + (size_t)(s * 64 + b) * GDIM + ct * 8 + hl;
#pragma unroll
            for (int g = 0; g < 4; g++) xr[p][g] = __ldg(xp + g * 512);
        }

        float acc[2][4];
#pragma unroll
        for (int nt = 0; nt < 2; nt++)
#pragma unroll
            for (int d = 0; d < 4; d++) acc[nt][d] = 0.f;

        // wait group A: segs 0-1 on kc 0-3
        asm volatile("cp.async.wait_group 2;" ::: "memory");
        __syncthreads();
#pragma unroll
        for (int seg = 0; seg < 2; seg++) {
            const int pb = (seg == 1) ? 8 : 0;
#pragma unroll
            for (int kc = 0; kc < 4; kc++) {
                const uint32_t abase = sb + kc * 8192;
                const uint32_t bbase = sb + SM_B_OFF + (pb + kc) * 4096;
#pragma unroll
                for (int ks = 0; ks < 4; ks++) {
                    uint32_t af[4], bf[4];
                    {
                        int r = wm * 16 + (lane & 15);
                        int q = 2 * ks + (lane >> 4);
                        ldm4(af, abase + r * 128 + ((q ^ (r & 7)) << 4));
                    }
                    {
                        int r = wn * 16 + (lane >> 4) * 8 + (lane & 7);
                        int q = 2 * ks + ((lane >> 3) & 1);
                        ldm4(bf, bbase + r * 128 + ((q ^ (r & 7)) << 4));
                    }
                    mma16816(acc[0], af, &bf[0]);
                    mma16816(acc[1], af, &bf[2]);
                }
            }
        }
        // wait group B: segs 0-1 on kc 4-7
        asm volatile("cp.async.wait_group 1;" ::: "memory");
        __syncthreads();
#pragma unroll
        for (int seg = 0; seg < 2; seg++) {
            const int pb = (seg == 1) ? 8 : 0;
#pragma unroll
            for (int kc = 4; kc < 8; kc++) {
                const uint32_t abase = sb + kc * 8192;
                const uint32_t bbase = sb + SM_B_OFF + (pb + kc) * 4096;
#pragma unroll
                for (int ks = 0; ks < 4; ks++) {
                    uint32_t af[4], bf[4];
                    {
                        int r = wm * 16 + (lane & 15);
                        int q = 2 * ks + (lane >> 4);
                        ldm4(af, abase + r * 128 + ((q ^ (r & 7)) << 4));
                    }
                    {
                        int r = wn * 16 + (lane >> 4) * 8 + (lane & 7);
                        int q = 2 * ks + ((lane >> 3) & 1);
                        ldm4(bf, bbase + r * 128 + ((q ^ (r & 7)) << 4));
                    }
                    mma16816(acc[0], af, &bf[0]);
                    mma16816(acc[1], af, &bf[2]);
                }
            }
        }
        // wait group C: seg 2 (lo(h) x hi(W))
        asm volatile("cp.async.wait_group 0;" ::: "memory");
        __syncthreads();
#pragma unroll
        for (int kc = 0; kc < 8; kc++) {
            const uint32_t abase = sb + (8 + kc) * 8192;
            const uint32_t bbase = sb + SM_B_OFF + kc * 4096;
#pragma unroll
            for (int ks = 0; ks < 4; ks++) {
                uint32_t af[4], bf[4];
                {
                    int r = wm * 16 + (lane & 15);
                    int q = 2 * ks + (lane >> 4);
                    ldm4(af, abase + r * 128 + ((q ^ (r & 7)) << 4));
                }
                {
                    int r = wn * 16 + (lane >> 4) * 8 + (lane & 7);
                    int q = 2 * ks + ((lane >> 3) & 1);
                    ldm4(bf, bbase + r * 128 + ((q ^ (r & 7)) << 4));
                }
                mma16816(acc[0], af, &bf[0]);
                mma16816(acc[1], af, &bf[2]);
            }
        }

#pragma unroll
        for (int nt = 0; nt < 2; nt++) {
            int col = wn * 16 + nt * 8 + (lane & 3) * 2;
            int row = wm * 16 + (lane >> 2);
            gs[row * 33 + col]           = acc[nt][0];
            gs[row * 33 + col + 1]       = acc[nt][1];
            gs[(row + 8) * 33 + col]     = acc[nt][2];
            gs[(row + 8) * 33 + col + 1] = acc[nt][3];
        }
        __syncthreads();

#pragma unroll
        for (int p = 0; p < 2; p++) {
            int idx = tid + p * 256;
            int b = idx & 63, hl = idx >> 6;
            float gi = gs[b * 33 + hl * 4 + 0] + xr[p][0];
            float gf = gs[b * 33 + hl * 4 + 1] + xr[p][1];
            float gg = gs[b * 33 + hl * 4 + 2] + xr[p][2];
            float go = gs[b * 33 + hl * 4 + 3] + xr[p][3];
            float iv = sigf(gi), fv = sigf(gf), gv = tanhfast(gg), ov = sigf(go);
            float cc = (p ? c1 : c0);
            cc = fv * cc + iv * gv;
            if (p) c1 = cc; else c0 = cc;
            float hv = ov * tanhfast(cc);
            __nv_bfloat16 hbv = __float2bfloat16(hv);
            __nv_bfloat16 lbv = __float2bfloat16(hv - __bfloat162float(hbv));
            hex[b * 8 + hl]       = hbv;
            hex[512 + b * 8 + hl] = lbv;
        }
        __syncthreads();

        // coalesced 16B global stores
        if (tid < 128) {
            int half = tid >> 6, b = tid & 63;
            uint4 v = *(const uint4*)(hex + half * 512 + b * 8);
            __nv_bfloat16* hbn = hb + (cur ^ 1) * (BATCH * 1024);
            *(uint4*)(hbn + (size_t)b * 1024 + half * 512 + ct * 8) = v;
            if (s >= TSTEPS) {
                int t = s - TSTEPS;
                *(uint4*)(hh2 + (size_t)(t * 64 + b) * 1024 + half * 512 + ct * 8) = v;
            }
        }

        gsync_tree(gen); gen++;
        cur ^= 1;
    }
}

// ---------------- launch ----------------
extern "C" void kernel_launch(void* const* d_in, const int* in_sizes, int n_in,
                              void* d_out, int out_size)
{
    const float* feats   = (const float*)d_in[0];
    const int*   labels  = (const int*)  d_in[1];
    const float* W_frame = (const float*)d_in[2];
    const float* b_frame = (const float*)d_in[3];
    const float* embed   = (const float*)d_in[4];
    const float* W_ih    = (const float*)d_in[5];
    const float* W_hh    = (const float*)d_in[6];
    const float* b_ih    = (const float*)d_in[7];
    const float* b_hh    = (const float*)d_in[8];
    const float* W_out   = (const float*)d_in[9];
    const float* b_out   = (const float*)d_in[10];
    float* out = (float*)d_out;

    float* p_xgate;
    __nv_bfloat16 *p_feats2, *p_Wf2, *p_emb2, *p_Wih2e, *p_Wih2d, *p_dece2, *p_Whh2, *p_hh2, *p_Wo2, *p_hb;
    cudaGetSymbolAddress((void**)&p_xgate,  g_xgate);
    cudaGetSymbolAddress((void**)&p_feats2, g_feats2);
    cudaGetSymbolAddress((void**)&p_Wf2,    g_Wf2);
    cudaGetSymbolAddress((void**)&p_emb2,   g_emb2);
    cudaGetSymbolAddress((void**)&p_Wih2e,  g_Wih2e);
    cudaGetSymbolAddress((void**)&p_Wih2d,  g_Wih2d);
    cudaGetSymbolAddress((void**)&p_dece2,  g_dece2);
    cudaGetSymbolAddress((void**)&p_Whh2,   g_Whh2);
    cudaGetSymbolAddress((void**)&p_hh2,    g_hh2);
    cudaGetSymbolAddress((void**)&p_Wo2,    g_Wo2);
    cudaGetSymbolAddress((void**)&p_hb,     g_hbufb);

    cudaFuncSetAttribute(lstm_tc, cudaFuncAttributeMaxDynamicSharedMemorySize, LSMEM);
    const int smem_tc = 2 * STG;   // 192KB
    cudaFuncSetAttribute(mma_tc, cudaFuncAttributeMaxDynamicSharedMemorySize, smem_tc);

    // [0] prep
    prep_all<<<1480, 256>>>(labels, embed, W_frame, W_ih, W_out, W_hh, feats,
                            p_Wf2, p_Wih2e, p_Wih2d, p_Wo2, p_dece2, p_Whh2, p_feats2);
    // [1] frame embedding -> g_emb2 (bf16 dual, t-major rows), K=4096
    {
        dim3 grid(MROWS / 128, EDIM / 256);
        mma_tc<<<grid, 256, smem_tc>>>(p_feats2, nullptr, 1 << 30, 0, p_Wf2, nullptr,
                                       b_frame, nullptr, p_emb2, FDIM, EDIM, 2 * EDIM, 2, 1);
    }
    // [2] both x-gate GEMMs fused (enc m-blocks 0-39, dec 40-79), K=512
    {
        dim3 grid(2 * (MROWS / 128), GDIM / 256);
        mma_tc<<<grid, 256, smem_tc>>>(p_emb2, p_dece2, MROWS / 128, MROWS,
                                       p_Wih2e, p_Wih2d, b_ih, b_hh,
                                       p_xgate, EDIM, GDIM, GDIM, 0, 0);
    }
    // [3] recurrence  <-- profiled launch
    lstm_tc<<<LCTAS, 256, LSMEM>>>(p_Whh2, p_xgate, p_hh2, p_hb);
    // [4] logits, K=512, t-major -> b-major remap
    {
        dim3 grid(MROWS / 128, VPAD / 256);
        mma_tc<<<grid, 256, smem_tc>>>(p_hh2, nullptr, 1 << 30, 0, p_Wo2, nullptr,
                                       b_out, nullptr, out, HDIM, VDIM, VDIM, 1, 0);
    }
}